// round 13
// baseline (speedup 1.0000x reference)
#include <cuda_runtime.h>
#include <cuda_fp16.h>
#include <cuda_fp8.h>
#include <mma.h>
#include <math.h>
#include <stdint.h>

using namespace nvcuda;

#define NS 305
#define SP 320
#define SPSP (SP * SP)
#define NB 64
#define NT 4096
#define NSTEP 819            // 5-gram supersteps: 1 + 5*819 = 4096 exactly
#define NMAT 256             // 4^4 composite matrices
#define LOG_SCALE_D 8.317766166719343   // log(4096)
#define DITH1 1.0471f        // dither factor for copy 1 (compensated exactly via g_rs)

// ---------------- device globals (zero-initialized) ----------------
__device__ float g_I[SP];
__device__ __align__(16) float g_BmT[4][SP];              // BmT[a][s] = Bm[s][a]
__device__ __align__(16) __half g_A16[SPSP];              // softmax(A), fp16
__device__ __align__(16) __half g_Q16[4][SPSP];           // Q_a = (A Da) A
__device__ __align__(16) __half g_U16[16][SPSP];          // U_cd = (Q_c Dd) A
__device__ __align__(16) __half g_M16[(size_t)NMAT * SPSP];  // M_abcd = (Q_a Db) U_cd
// e5m2, 2 dither copies, 16-col BLOCKED layout (R7): byte (r,c) at
// ((r>>5)*20 + (c>>4))*512 + (r&31)*16 + (c&15)
// => warp-uniform uint4 load address base + tid + 640k (fully coalesced, 4 lines/warp)
__device__ __align__(16) unsigned char g_S[2ull * NMAT * SPSP];
__device__ __align__(16) float g_rs[2 * NMAT * SP];       // alpha row multiplier 4096/q per copy
__device__ unsigned short g_gram[NB * NSTEP];             // (z<<2)|fold, z in 0..255
__device__ unsigned char g_o0[NB];

__device__ __forceinline__ float warpSum(float x) {
    #pragma unroll
    for (int o = 16; o; o >>= 1) x += __shfl_down_sync(0xffffffffu, x, o);
    return x;
}
__device__ __forceinline__ float warpMax(float x) {
    #pragma unroll
    for (int o = 16; o; o >>= 1) x = fmaxf(x, __shfl_down_sync(0xffffffffu, x, o));
    return x;
}
__device__ __forceinline__ float warpMaxAll(float x) {
    #pragma unroll
    for (int o = 16; o; o >>= 1) x = fmaxf(x, __shfl_xor_sync(0xffffffffu, x, o));
    return x;
}
__device__ __forceinline__ __half2 u2h(uint32_t u) { return *reinterpret_cast<__half2*>(&u); }
__device__ __forceinline__ uint32_t h2u(__half2 h) { return *reinterpret_cast<uint32_t*>(&h); }
__device__ __forceinline__ uint32_t hadd2u(uint32_t a, uint32_t b) {
    return h2u(__hadd2(u2h(a), u2h(b)));
}

#define BAR_SYNC(id, n)   asm volatile("bar.sync %0, %1;"   :: "n"(id), "n"(n) : "memory")

// ---------------- setup: I softmax + emission softmax ----------------
__global__ void k_setup(const float* __restrict__ initk, const float* __restrict__ emisk) {
    __shared__ float red[16];
    __shared__ float bval;
    int tid = threadIdx.x, wid = tid >> 5, lane = tid & 31;
    const int nw = 16;
    float v = (tid < NS) ? initk[tid] : -1e30f;
    float m = warpMax(v);
    if (lane == 0) red[wid] = m;
    __syncthreads();
    if (tid == 0) { float mm = -1e30f; for (int w = 0; w < nw; w++) mm = fmaxf(mm, red[w]); bval = mm; }
    __syncthreads();
    m = bval;
    float e = (tid < NS) ? expf(v - m) : 0.f;
    float s = warpSum(e);
    __syncthreads();
    if (lane == 0) red[wid] = s;
    __syncthreads();
    if (tid == 0) { float ss = 0.f; for (int w = 0; w < nw; w++) ss += red[w]; bval = ss; }
    __syncthreads();
    if (tid < NS) g_I[tid] = e / bval;

    if (tid < NS) {
        float x0 = emisk[tid * 4 + 0], x1 = emisk[tid * 4 + 1];
        float x2 = emisk[tid * 4 + 2], x3 = emisk[tid * 4 + 3];
        float mm = fmaxf(fmaxf(x0, x1), fmaxf(x2, x3));
        float e0 = expf(x0 - mm), e1 = expf(x1 - mm), e2 = expf(x2 - mm), e3 = expf(x3 - mm);
        float inv = 1.f / (e0 + e1 + e2 + e3);
        g_BmT[0][tid] = e0 * inv; g_BmT[1][tid] = e1 * inv;
        g_BmT[2][tid] = e2 * inv; g_BmT[3][tid] = e3 * inv;
    }
}

// ---------------- softmax rows of transition -> A16 ----------------
__global__ void k_softA(const float* __restrict__ trans) {
    __shared__ float red[10];
    __shared__ float bval;
    int r = blockIdx.x, tid = threadIdx.x;
    int wid = tid >> 5, lane = tid & 31;
    float v = (tid < NS) ? trans[r * NS + tid] : -1e30f;
    float m = warpMax(v);
    if (lane == 0) red[wid] = m;
    __syncthreads();
    if (tid == 0) { float mm = -1e30f; for (int w = 0; w < 10; w++) mm = fmaxf(mm, red[w]); bval = mm; }
    __syncthreads();
    m = bval;
    float e = (tid < NS) ? expf(v - m) : 0.f;
    float s = warpSum(e);
    __syncthreads();
    if (lane == 0) red[wid] = s;
    __syncthreads();
    if (tid == 0) { float ss = 0.f; for (int w = 0; w < 10; w++) ss += red[w]; bval = ss; }
    __syncthreads();
    if (tid < NS) g_A16[r * SP + tid] = __float2half_rn(e / bval);
}

// ---------------- observation -> 5-gram indices ----------------
__global__ void k_gram(const float* __restrict__ inputs) {
    int b = blockIdx.x;
    const float* inb = inputs + (size_t)b * NT * 4;
    for (int tau = threadIdx.x; tau < NSTEP; tau += blockDim.x) {
        int t0 = 1 + 5 * tau;
        unsigned g = 0;
        #pragma unroll
        for (int k = 0; k < 5; k++) {
            const float* p = inb + (size_t)(t0 + k) * 4;
            float fi = p[1] + 2.f * p[2] + 3.f * p[3];   // exact argmax of one-hot
            g = (g << 2) | (unsigned)(fi + 0.5f);
        }
        g_gram[b * NSTEP + tau] = (unsigned short)g;      // z = g>>2 (8b), fold = g&3
    }
    if (threadIdx.x == 0) {
        const float* p = inb;
        g_o0[b] = (unsigned char)(p[1] + 2.f * p[2] + 3.f * p[3] + 0.5f);
    }
}

// ---------------- wmma fp16 GEMM: C = (L * diag(sc)) @ R, all [320,320] half ----------------
// mode 0: Q_z = (A*Dz)@A (z<4); mode 1: U_z = (Q_{z>>2}*D_{z&3})@A (z<16);
// mode 2: M_z = (Q_{z>>6}*D_{(z>>4)&3})@U_{z&15} (z<256)
__global__ void __launch_bounds__(256) k_gemm_h(int mode) {
    int z = blockIdx.z;
    const __half *Lp, *Rp;
    const float* sc;
    __half* outp;
    if (mode == 0)      { Lp = g_A16;        sc = g_BmT[z];           Rp = g_A16;        outp = g_Q16[z]; }
    else if (mode == 1) { Lp = g_Q16[z >> 2]; sc = g_BmT[z & 3];      Rp = g_A16;        outp = g_U16[z]; }
    else                { Lp = g_Q16[z >> 6]; sc = g_BmT[(z >> 4) & 3]; Rp = g_U16[z & 15]; outp = g_M16 + (size_t)z * SPSP; }
    int m0 = blockIdx.y * 64, n0 = blockIdx.x * 64;

    __shared__ __align__(16) __half As[64][72];
    __shared__ __align__(16) __half Bs[64][72];
    __shared__ __align__(16) float Cs[64][68];

    int tid = threadIdx.x;
    int w = tid >> 5;
    int wm = w & 3, wn = w >> 2;                 // 4 M-blocks x 2 N-blocks (16x32 per warp)
    int lr = tid >> 2, lc = (tid & 3) * 16;

    wmma::fragment<wmma::accumulator, 16, 16, 16, float> cf[2];
    wmma::fill_fragment(cf[0], 0.f);
    wmma::fill_fragment(cf[1], 0.f);

    for (int k0 = 0; k0 < SP; k0 += 64) {
        #pragma unroll
        for (int j = 0; j < 16; j += 2) {
            __half2 lv = *(const __half2*)&Lp[(size_t)(m0 + lr) * SP + k0 + lc + j];
            float2 sv = *(const float2*)&sc[k0 + lc + j];
            float2 lf = __half22float2(lv);
            *(__half2*)&As[lr][lc + j] = __floats2half2_rn(lf.x * sv.x, lf.y * sv.y);
            *(__half2*)&Bs[lr][lc + j] = *(const __half2*)&Rp[(size_t)(k0 + lr) * SP + n0 + lc + j];
        }
        __syncthreads();
        #pragma unroll
        for (int kk = 0; kk < 4; kk++) {
            wmma::fragment<wmma::matrix_a, 16, 16, 16, __half, wmma::row_major> af;
            wmma::load_matrix_sync(af, &As[wm * 16][kk * 16], 72);
            #pragma unroll
            for (int nn = 0; nn < 2; nn++) {
                wmma::fragment<wmma::matrix_b, 16, 16, 16, __half, wmma::row_major> bf;
                wmma::load_matrix_sync(bf, &Bs[kk * 16][wn * 32 + nn * 16], 72);
                wmma::mma_sync(cf[nn], af, bf, cf[nn]);
            }
        }
        __syncthreads();
    }
    wmma::store_matrix_sync(&Cs[wm * 16][wn * 32 + 0], cf[0], 68, wmma::mem_row_major);
    wmma::store_matrix_sync(&Cs[wm * 16][wn * 32 + 16], cf[1], 68, wmma::mem_row_major);
    __syncthreads();
    #pragma unroll
    for (int j = 0; j < 16; j++)
        outp[(size_t)(m0 + lr) * SP + n0 + lc + j] = __float2half_rn(Cs[lr][lc + j]);
}

// ---------------- quantize M to e5m2, warp-per-row, 16-col blocked, BOTH copies in one pass ----
// grid (40, 256), block 256 (8 warps; warp handles row blockIdx.x*8+warp)
__global__ void k_quant() {
    int z = blockIdx.y;
    int warp = threadIdx.x >> 5, lane = threadIdx.x & 31;
    int r = blockIdx.x * 8 + warp;
    const __half* row = g_M16 + (size_t)z * SPSP + (size_t)r * SP;

    float vv[10];
    float mx = 0.f;
    #pragma unroll
    for (int i = 0; i < 10; i++) { vv[i] = __half2float(row[lane + 32 * i]); mx = fmaxf(mx, vv[i]); }
    mx = warpMaxAll(mx);
    float q0 = (mx > 0.f) ? 384.f / mx : 1.f;
    float q1 = q0 * DITH1;
    unsigned char* dst0 = g_S + (size_t)z * SPSP;
    unsigned char* dst1 = g_S + ((size_t)NMAT + z) * SPSP;
    int rk = r >> 5, rL = r & 31;
    #pragma unroll
    for (int i = 0; i < 10; i++) {
        int col = lane + 32 * i;
        uint32_t off = (((rk * 20 + (col >> 4)) * 32 + rL) << 4) + (col & 15);
        dst0[off] = (unsigned char)__nv_cvt_float_to_fp8(vv[i] * q0, __NV_SATFINITE, __NV_E5M2);
        dst1[off] = (unsigned char)__nv_cvt_float_to_fp8(vv[i] * q1, __NV_SATFINITE, __NV_E5M2);
    }
    if (lane == 0) {
        g_rs[z * SP + r] = 4096.f / q0;
        g_rs[(NMAT + z) * SP + r] = 4096.f / q1;
    }
}

// ---------------- chain: single-CTA per batch (R7 structure), 819 supersteps ----------------
// 20 warps. Warp w owns cols [16w,16w+16); lane = row-class (rows lane+32k). One bar.sync/step.
// Deferred-si: ah2 unnormalized; si_prev computed redundantly by every warp from redp at iter
// top; warp writes only its own ah2 slice pre-barrier. Double-buffered ah2+redp => race-free.
__global__ void __launch_bounds__(640, 1) k_chain(float* __restrict__ out) {
    int b = blockIdx.x, tid = threadIdx.x;
    __shared__ __half2 ah2[2][SP];
    __shared__ __align__(16) float redp[2][24];    // 96B rows keep float4 alignment
    __shared__ unsigned short sg[NSTEP + 1];
    int lane = tid & 31, w = tid >> 5;

    for (int i = tid; i < NSTEP; i += 640) sg[i] = g_gram[b * NSTEP + i];
    int o0 = g_o0[b];
    if (tid == 0) sg[NSTEP] = 0;                   // sentinel for step+1 lookahead
    if (tid < 24) { redp[0][tid] = 0.f; redp[1][tid] = (tid == 0) ? 1.f : 0.f; }
    __syncthreads();
    int z0 = sg[0] >> 2;

    // ---- prologue: alpha0 = normalize(I * Bm[:,o0]) -> ah2[0] (fully normalized) ----
    float llf = 0.f, lcomp = 0.f;
    {
        __shared__ float pr[20];
        __shared__ float psinv;
        __shared__ float af[SP];
        float v0p = (tid < SP) ? g_I[tid] * g_BmT[o0][tid] : 0.f;
        float wsum = warpSum(v0p);
        if (lane == 0) pr[w] = wsum;
        __syncthreads();
        if (tid == 0) {
            float x = 0.f;
            #pragma unroll
            for (int q = 0; q < 20; q++) x += pr[q];
            psinv = 1.f / x;
            pr[0] = x;
        }
        __syncthreads();
        llf = logf(pr[0]);
        if (tid < SP) af[tid] = v0p * psinv;
        __syncthreads();
        if (tid < 160) {
            float2 rsv = *(const float2*)&g_rs[z0 * SP + 2 * tid];   // step 0 = copy 0
            float a0 = af[2 * tid] * rsv.x, a1 = af[2 * tid + 1] * rsv.y;
            ah2[0][2 * tid]     = __floats2half2_rn(a0, a0);
            ah2[0][2 * tid + 1] = __floats2half2_rn(a1, a1);
        }
        __syncthreads();
    }

    // ---- preload matrix regs for step 0 (copy 0) ----
    uint4 mr[10];
    {
        const uint4* p = (const uint4*)(g_S + (size_t)z0 * SPSP) + tid;
        #pragma unroll
        for (int k = 0; k < 10; k++) mr[k] = __ldcg(p + k * 640);
    }

    int bit0 = lane & 1, bit1 = (lane >> 1) & 1, bit2 = (lane >> 2) & 1;
    int j8 = lane & 7;

    for (int step = 0; step < NSTEP; ++step) {
        int pb = step & 1, nb = 1 - pb;
        int d = sg[step] & 3;
        int zn = sg[step + 1] >> 2;                // sentinel makes last lookahead safe
        int zoff = nb * NMAT + zn;                 // dither copy alternates by step

        // si_prev from last step's totals (buffer nb holds s_{step-1}; init => 1 at step 0)
        float4 q0 = *(const float4*)&redp[nb][0];
        float4 q1 = *(const float4*)&redp[nb][4];
        float4 q2 = *(const float4*)&redp[nb][8];
        float4 q3 = *(const float4*)&redp[nb][12];
        float4 q4 = *(const float4*)&redp[nb][16];
        float tot = ((q0.x + q0.y) + (q0.z + q0.w)) + ((q1.x + q1.y) + (q1.z + q1.w))
                  + ((q2.x + q2.y) + (q2.z + q2.w)) + ((q3.x + q3.y) + (q3.z + q3.w))
                  + ((q4.x + q4.y) + (q4.z + q4.w));
        float si = __frcp_rn(tot);
        if (tid == 0) {                            // Kahan log of s_{step-1} (log(1)=0 at step 0)
            float y = logf(tot) - lcomp;
            float t2 = llf + y;
            lcomp = (t2 - llf) - y;
            llf = t2;
        }

        // prefetch fold (this step) + next row-scales (own 2 states)
        float2 fo  = *(const float2*)&g_BmT[d][16 * w + 2 * j8];
        float2 rsv = *(const float2*)&g_rs[(size_t)zoff * SP + 16 * w + 2 * j8];

        // ---- FMA phase: warp w, cols 16w..16w+15; lane rows lane+32k (reads ah2[pb]) ----
        __half2 a0 = __floats2half2_rn(0.f, 0.f);
        __half2 a1 = a0, a2 = a0, a3 = a0, a4 = a0, a5 = a0, a6 = a0, a7 = a0;
        #pragma unroll
        for (int k = 0; k < 10; k++) {
            __half2 av = ah2[pb][lane + 32 * k];
            a0 = __hfma2(av, u2h(__byte_perm(mr[k].x, 0, 0x1404)), a0);
            a1 = __hfma2(av, u2h(__byte_perm(mr[k].x, 0, 0x3424)), a1);
            a2 = __hfma2(av, u2h(__byte_perm(mr[k].y, 0, 0x1404)), a2);
            a3 = __hfma2(av, u2h(__byte_perm(mr[k].y, 0, 0x3424)), a3);
            a4 = __hfma2(av, u2h(__byte_perm(mr[k].z, 0, 0x1404)), a4);
            a5 = __hfma2(av, u2h(__byte_perm(mr[k].z, 0, 0x3424)), a5);
            a6 = __hfma2(av, u2h(__byte_perm(mr[k].w, 0, 0x1404)), a6);
            a7 = __hfma2(av, u2h(__byte_perm(mr[k].w, 0, 0x3424)), a7);
        }

        // ---- issue next step's matrix loads (mr regs now free) ----
        {
            const uint4* p = (const uint4*)(g_S + (size_t)zoff * SPSP) + tid;
            #pragma unroll
            for (int k = 0; k < 10; k++) mr[k] = __ldcg(p + k * 640);
        }

        // ---- in-warp reg-halving reduce: all lanes end with col pair j = lane&7 ----
        uint32_t h0 = h2u(a0), h1 = h2u(a1), h2v = h2u(a2), h3 = h2u(a3);
        uint32_t h4 = h2u(a4), h5 = h2u(a5), h6 = h2u(a6), h7 = h2u(a7);
        {
            uint32_t g0 = bit0 ? h0 : h1, g1 = bit0 ? h2v : h3;
            uint32_t g2 = bit0 ? h4 : h5, g3 = bit0 ? h6 : h7;
            uint32_t r0 = __shfl_xor_sync(0xffffffffu, g0, 1);
            uint32_t r1 = __shfl_xor_sync(0xffffffffu, g1, 1);
            uint32_t r2 = __shfl_xor_sync(0xffffffffu, g2, 1);
            uint32_t r3 = __shfl_xor_sync(0xffffffffu, g3, 1);
            h0 = hadd2u(bit0 ? h1 : h0, r0);
            h1 = hadd2u(bit0 ? h3 : h2v, r1);
            h2v = hadd2u(bit0 ? h5 : h4, r2);
            h3 = hadd2u(bit0 ? h7 : h6, r3);
        }
        {
            uint32_t g0 = bit1 ? h0 : h1, g1 = bit1 ? h2v : h3;
            uint32_t r0 = __shfl_xor_sync(0xffffffffu, g0, 2);
            uint32_t r1 = __shfl_xor_sync(0xffffffffu, g1, 2);
            h0 = hadd2u(bit1 ? h1 : h0, r0);
            h1 = hadd2u(bit1 ? h3 : h2v, r1);
        }
        {
            uint32_t g0 = bit2 ? h0 : h1;
            uint32_t r0 = __shfl_xor_sync(0xffffffffu, g0, 4);
            h0 = hadd2u(bit2 ? h1 : h0, r0);
        }
        h0 = hadd2u(h0, __shfl_xor_sync(0xffffffffu, h0, 8));
        h0 = hadd2u(h0, __shfl_xor_sync(0xffffffffu, h0, 16));

        // lanes 0-7: finish own 2 states — apply fold + si_prev, write ah2[nb] slice
        float p = 0.f;
        if (lane < 8) {
            float2 f2 = __half22float2(u2h(h0));
            float v0 = f2.x * fo.x * si, v1 = f2.y * fo.y * si;
            float b0 = v0 * rsv.x, b1 = v1 * rsv.y;     // next alpha, un-si'd (deferred)
            uint2 packed;
            packed.x = h2u(__floats2half2_rn(b0, b0));
            packed.y = h2u(__floats2half2_rn(b1, b1));
            *(uint2*)&ah2[nb][16 * w + 2 * j8] = packed;
            p = v0 + v1;                                 // contribution to s_step
        }
        p += __shfl_xor_sync(0xffffffffu, p, 1);
        p += __shfl_xor_sync(0xffffffffu, p, 2);
        p += __shfl_xor_sync(0xffffffffu, p, 4);
        if (lane == 0) redp[pb][w] = p;                  // publish s_step partial

        BAR_SYNC(1, 640);                                // the ONLY barrier per step
    }
    __syncthreads();
    if (tid == 0) {
        int fb = (NSTEP - 1) & 1;                        // buffer holding s_{NSTEP-1}
        float tot = 0.f;
        #pragma unroll
        for (int q = 0; q < 20; q++) tot += redp[fb][q];
        llf += logf(tot);
        out[b] = (float)((double)llf - (double)NSTEP * LOG_SCALE_D);
    }
}

// ---------------- launch ----------------
extern "C" void kernel_launch(void* const* d_in, const int* in_sizes, int n_in,
                              void* d_out, int out_size) {
    const float* inputs = (const float*)d_in[0];
    const float* initk  = (const float*)d_in[1];
    const float* transk = (const float*)d_in[2];
    const float* emisk  = (const float*)d_in[3];
    float* out = (float*)d_out;

    k_setup<<<1, 512>>>(initk, emisk);
    k_softA<<<NS, 320>>>(transk);
    k_gram<<<NB, 256>>>(inputs);
    k_gemm_h<<<dim3(5, 5, 4), 256>>>(0);     // Q_a
    k_gemm_h<<<dim3(5, 5, 16), 256>>>(1);    // U_cd
    k_gemm_h<<<dim3(5, 5, 256), 256>>>(2);   // M_abcd
    k_quant<<<dim3(40, 256), 256>>>();
    k_chain<<<NB, 640>>>(out);
}

// round 14
// speedup vs baseline: 1.0562x; 1.0562x over previous
#include <cuda_runtime.h>
#include <cuda_fp16.h>
#include <cuda_fp8.h>
#include <mma.h>
#include <math.h>
#include <stdint.h>

using namespace nvcuda;

#define NS 305
#define SP 320
#define SPSP (SP * SP)
#define NB 64
#define NT 4096
#define NSTEP 819            // 5-gram supersteps: 1 + 5*819 = 4096 exactly
#define NMAT 256             // 4^4 composite matrices
#define LOG_SCALE_D 8.317766166719343   // log(4096)

// ---------------- device globals (zero-initialized) ----------------
__device__ float g_I[SP];
__device__ __align__(16) float g_BmT[4][SP];              // BmT[a][s] = Bm[s][a]
__device__ __align__(16) __half g_A16[SPSP];              // softmax(A), fp16
__device__ __align__(16) __half g_Q16[4][SPSP];           // Q_a = (A Da) A
__device__ __align__(16) __half g_U16[16][SPSP];          // U_cd = (Q_c Dd) A
__device__ __align__(16) __half g_M16[(size_t)NMAT * SPSP];  // M_abcd = (Q_a Db) U_cd
// e5m2 SINGLE copy (26 MB -> L2-resident), 16-col blocked: byte (r,c) at
// ((r>>5)*20 + (c>>4))*512 + (r&31)*16 + (c&15)
__device__ __align__(16) unsigned char g_S[(size_t)NMAT * SPSP];
// rs[(z*4+d)*SP + r] = 4096 * (sum_j BmT[d][j]*M[z][r][j]) / (sum_j BmT[d][j]*dec(S[z][r][j]))
// exact per-(z,d,row) bias cancellation folded with the 4096 scale
__device__ __align__(16) float g_rs[NMAT * 4 * SP];
__device__ unsigned short g_gram[NB * NSTEP];             // (z<<2)|fold, z in 0..255
__device__ unsigned char g_o0[NB];

__device__ __forceinline__ float warpSum(float x) {
    #pragma unroll
    for (int o = 16; o; o >>= 1) x += __shfl_down_sync(0xffffffffu, x, o);
    return x;
}
__device__ __forceinline__ float warpSumAll(float x) {
    #pragma unroll
    for (int o = 16; o; o >>= 1) x += __shfl_xor_sync(0xffffffffu, x, o);
    return x;
}
__device__ __forceinline__ float warpMax(float x) {
    #pragma unroll
    for (int o = 16; o; o >>= 1) x = fmaxf(x, __shfl_down_sync(0xffffffffu, x, o));
    return x;
}
__device__ __forceinline__ float warpMaxAll(float x) {
    #pragma unroll
    for (int o = 16; o; o >>= 1) x = fmaxf(x, __shfl_xor_sync(0xffffffffu, x, o));
    return x;
}
__device__ __forceinline__ __half2 u2h(uint32_t u) { return *reinterpret_cast<__half2*>(&u); }
__device__ __forceinline__ uint32_t h2u(__half2 h) { return *reinterpret_cast<uint32_t*>(&h); }
__device__ __forceinline__ uint32_t hadd2u(uint32_t a, uint32_t b) {
    return h2u(__hadd2(u2h(a), u2h(b)));
}

#define BAR_SYNC(id, n)   asm volatile("bar.sync %0, %1;"   :: "n"(id), "n"(n) : "memory")

// ---------------- setup: I softmax + emission softmax ----------------
__global__ void k_setup(const float* __restrict__ initk, const float* __restrict__ emisk) {
    __shared__ float red[16];
    __shared__ float bval;
    int tid = threadIdx.x, wid = tid >> 5, lane = tid & 31;
    const int nw = 16;
    float v = (tid < NS) ? initk[tid] : -1e30f;
    float m = warpMax(v);
    if (lane == 0) red[wid] = m;
    __syncthreads();
    if (tid == 0) { float mm = -1e30f; for (int w = 0; w < nw; w++) mm = fmaxf(mm, red[w]); bval = mm; }
    __syncthreads();
    m = bval;
    float e = (tid < NS) ? expf(v - m) : 0.f;
    float s = warpSum(e);
    __syncthreads();
    if (lane == 0) red[wid] = s;
    __syncthreads();
    if (tid == 0) { float ss = 0.f; for (int w = 0; w < nw; w++) ss += red[w]; bval = ss; }
    __syncthreads();
    if (tid < NS) g_I[tid] = e / bval;

    if (tid < NS) {
        float x0 = emisk[tid * 4 + 0], x1 = emisk[tid * 4 + 1];
        float x2 = emisk[tid * 4 + 2], x3 = emisk[tid * 4 + 3];
        float mm = fmaxf(fmaxf(x0, x1), fmaxf(x2, x3));
        float e0 = expf(x0 - mm), e1 = expf(x1 - mm), e2 = expf(x2 - mm), e3 = expf(x3 - mm);
        float inv = 1.f / (e0 + e1 + e2 + e3);
        g_BmT[0][tid] = e0 * inv; g_BmT[1][tid] = e1 * inv;
        g_BmT[2][tid] = e2 * inv; g_BmT[3][tid] = e3 * inv;
    }
}

// ---------------- softmax rows of transition -> A16 ----------------
__global__ void k_softA(const float* __restrict__ trans) {
    __shared__ float red[10];
    __shared__ float bval;
    int r = blockIdx.x, tid = threadIdx.x;
    int wid = tid >> 5, lane = tid & 31;
    float v = (tid < NS) ? trans[r * NS + tid] : -1e30f;
    float m = warpMax(v);
    if (lane == 0) red[wid] = m;
    __syncthreads();
    if (tid == 0) { float mm = -1e30f; for (int w = 0; w < 10; w++) mm = fmaxf(mm, red[w]); bval = mm; }
    __syncthreads();
    m = bval;
    float e = (tid < NS) ? expf(v - m) : 0.f;
    float s = warpSum(e);
    __syncthreads();
    if (lane == 0) red[wid] = s;
    __syncthreads();
    if (tid == 0) { float ss = 0.f; for (int w = 0; w < 10; w++) ss += red[w]; bval = ss; }
    __syncthreads();
    if (tid < NS) g_A16[r * SP + tid] = __float2half_rn(e / bval);
}

// ---------------- observation -> 5-gram indices ----------------
__global__ void k_gram(const float* __restrict__ inputs) {
    int b = blockIdx.x;
    const float* inb = inputs + (size_t)b * NT * 4;
    for (int tau = threadIdx.x; tau < NSTEP; tau += blockDim.x) {
        int t0 = 1 + 5 * tau;
        unsigned g = 0;
        #pragma unroll
        for (int k = 0; k < 5; k++) {
            const float* p = inb + (size_t)(t0 + k) * 4;
            float fi = p[1] + 2.f * p[2] + 3.f * p[3];   // exact argmax of one-hot
            g = (g << 2) | (unsigned)(fi + 0.5f);
        }
        g_gram[b * NSTEP + tau] = (unsigned short)g;      // z = g>>2 (8b), fold = g&3
    }
    if (threadIdx.x == 0) {
        const float* p = inb;
        g_o0[b] = (unsigned char)(p[1] + 2.f * p[2] + 3.f * p[3] + 0.5f);
    }
}

// ---------------- wmma fp16 GEMM: C = (L * diag(sc)) @ R, all [320,320] half ----------------
// mode 0: Q_z = (A*Dz)@A (z<4); mode 1: U_z = (Q_{z>>2}*D_{z&3})@A (z<16);
// mode 2: M_z = (Q_{z>>6}*D_{(z>>4)&3})@U_{z&15} (z<256)
__global__ void __launch_bounds__(256) k_gemm_h(int mode) {
    int z = blockIdx.z;
    const __half *Lp, *Rp;
    const float* sc;
    __half* outp;
    if (mode == 0)      { Lp = g_A16;        sc = g_BmT[z];           Rp = g_A16;        outp = g_Q16[z]; }
    else if (mode == 1) { Lp = g_Q16[z >> 2]; sc = g_BmT[z & 3];      Rp = g_A16;        outp = g_U16[z]; }
    else                { Lp = g_Q16[z >> 6]; sc = g_BmT[(z >> 4) & 3]; Rp = g_U16[z & 15]; outp = g_M16 + (size_t)z * SPSP; }
    int m0 = blockIdx.y * 64, n0 = blockIdx.x * 64;

    __shared__ __align__(16) __half As[64][72];
    __shared__ __align__(16) __half Bs[64][72];
    __shared__ __align__(16) float Cs[64][68];

    int tid = threadIdx.x;
    int w = tid >> 5;
    int wm = w & 3, wn = w >> 2;                 // 4 M-blocks x 2 N-blocks (16x32 per warp)
    int lr = tid >> 2, lc = (tid & 3) * 16;

    wmma::fragment<wmma::accumulator, 16, 16, 16, float> cf[2];
    wmma::fill_fragment(cf[0], 0.f);
    wmma::fill_fragment(cf[1], 0.f);

    for (int k0 = 0; k0 < SP; k0 += 64) {
        #pragma unroll
        for (int j = 0; j < 16; j += 2) {
            __half2 lv = *(const __half2*)&Lp[(size_t)(m0 + lr) * SP + k0 + lc + j];
            float2 sv = *(const float2*)&sc[k0 + lc + j];
            float2 lf = __half22float2(lv);
            *(__half2*)&As[lr][lc + j] = __floats2half2_rn(lf.x * sv.x, lf.y * sv.y);
            *(__half2*)&Bs[lr][lc + j] = *(const __half2*)&Rp[(size_t)(k0 + lr) * SP + n0 + lc + j];
        }
        __syncthreads();
        #pragma unroll
        for (int kk = 0; kk < 4; kk++) {
            wmma::fragment<wmma::matrix_a, 16, 16, 16, __half, wmma::row_major> af;
            wmma::load_matrix_sync(af, &As[wm * 16][kk * 16], 72);
            #pragma unroll
            for (int nn = 0; nn < 2; nn++) {
                wmma::fragment<wmma::matrix_b, 16, 16, 16, __half, wmma::row_major> bf;
                wmma::load_matrix_sync(bf, &Bs[kk * 16][wn * 32 + nn * 16], 72);
                wmma::mma_sync(cf[nn], af, bf, cf[nn]);
            }
        }
        __syncthreads();
    }
    wmma::store_matrix_sync(&Cs[wm * 16][wn * 32 + 0], cf[0], 68, wmma::mem_row_major);
    wmma::store_matrix_sync(&Cs[wm * 16][wn * 32 + 16], cf[1], 68, wmma::mem_row_major);
    __syncthreads();
    #pragma unroll
    for (int j = 0; j < 16; j++)
        outp[(size_t)(m0 + lr) * SP + n0 + lc + j] = __float2half_rn(Cs[lr][lc + j]);
}

// ---------------- quantize M to e5m2 (single copy) + exact fold-weighted row corrections ----
// grid (40, 256), block 256 (8 warps; warp handles row blockIdx.x*8+warp).
// rs[(z*4+d)*SP+r] = 4096 * (sum_j BmT[d][j]*M[r][j]) / (sum_j BmT[d][j]*dec(byte[r][j]))
__global__ void k_quant() {
    int z = blockIdx.y;
    int warp = threadIdx.x >> 5, lane = threadIdx.x & 31;
    int r = blockIdx.x * 8 + warp;
    const __half* row = g_M16 + (size_t)z * SPSP + (size_t)r * SP;

    float vv[10];
    float mx = 0.f;
    #pragma unroll
    for (int i = 0; i < 10; i++) { vv[i] = __half2float(row[lane + 32 * i]); mx = fmaxf(mx, vv[i]); }
    mx = warpMaxAll(mx);
    float q = (mx > 0.f) ? 384.f / mx : 1.f;
    unsigned char* dst = g_S + (size_t)z * SPSP;
    int rk = r >> 5, rL = r & 31;

    float dec[10];
    #pragma unroll
    for (int i = 0; i < 10; i++) {
        int col = lane + 32 * i;
        unsigned char byte =
            (unsigned char)__nv_cvt_float_to_fp8(vv[i] * q, __NV_SATFINITE, __NV_E5M2);
        dst[(((rk * 20 + (col >> 4)) * 32 + rL) << 4) + (col & 15)] = byte;
        // decode: e5m2 -> f16 is byte<<8 (bit-exact, same trick the chain uses)
        dec[i] = __half2float(__ushort_as_half((unsigned short)(byte << 8)));
    }

    // fold-weighted true & quantized row sums for each d
    #pragma unroll
    for (int d = 0; d < 4; d++) {
        float st = 0.f, sq = 0.f;
        #pragma unroll
        for (int i = 0; i < 10; i++) {
            float bm = g_BmT[d][lane + 32 * i];
            st = fmaf(bm, vv[i], st);
            sq = fmaf(bm, dec[i], sq);
        }
        st = warpSumAll(st);
        sq = warpSumAll(sq);
        if (lane == 0)
            g_rs[(z * 4 + d) * SP + r] = (sq > 0.f) ? 4096.f * st / sq : 0.f;
    }
}

// ---------------- chain: single-CTA per batch, 819 supersteps, single e5m2 copy ----------------
// 20 warps. Warp w owns cols [16w,16w+16); lane = row-class (rows lane+32k). One bar.sync/step.
// Deferred-si; rs indexed by (z_{t+1}, d_{t+1}) gives exact per-step bias cancellation.
__global__ void __launch_bounds__(640, 1) k_chain(float* __restrict__ out) {
    int b = blockIdx.x, tid = threadIdx.x;
    __shared__ __half2 ah2[2][SP];
    __shared__ __align__(16) float redp[2][24];    // 96B rows keep float4 alignment
    __shared__ unsigned short sg[NSTEP + 1];
    int lane = tid & 31, w = tid >> 5;

    for (int i = tid; i < NSTEP; i += 640) sg[i] = g_gram[b * NSTEP + i];
    int o0 = g_o0[b];
    if (tid == 0) sg[NSTEP] = 0;                   // sentinel for step+1 lookahead
    if (tid < 24) { redp[0][tid] = 0.f; redp[1][tid] = (tid == 0) ? 1.f : 0.f; }
    __syncthreads();
    int z0 = sg[0] >> 2, d0 = sg[0] & 3;

    // ---- prologue: alpha0 = normalize(I * Bm[:,o0]) -> ah2[0], scaled by rs(z0,d0) ----
    float llf = 0.f, lcomp = 0.f;
    {
        __shared__ float pr[20];
        __shared__ float psinv;
        __shared__ float af[SP];
        float v0p = (tid < SP) ? g_I[tid] * g_BmT[o0][tid] : 0.f;
        float wsum = warpSum(v0p);
        if (lane == 0) pr[w] = wsum;
        __syncthreads();
        if (tid == 0) {
            float x = 0.f;
            #pragma unroll
            for (int q = 0; q < 20; q++) x += pr[q];
            psinv = 1.f / x;
            pr[0] = x;
        }
        __syncthreads();
        llf = logf(pr[0]);
        if (tid < SP) af[tid] = v0p * psinv;
        __syncthreads();
        if (tid < 160) {
            float2 rsv = *(const float2*)&g_rs[(z0 * 4 + d0) * SP + 2 * tid];
            float a0 = af[2 * tid] * rsv.x, a1 = af[2 * tid + 1] * rsv.y;
            ah2[0][2 * tid]     = __floats2half2_rn(a0, a0);
            ah2[0][2 * tid + 1] = __floats2half2_rn(a1, a1);
        }
        __syncthreads();
    }

    // ---- preload matrix regs for step 0 ----
    uint4 mr[10];
    {
        const uint4* p = (const uint4*)(g_S + (size_t)z0 * SPSP) + tid;
        #pragma unroll
        for (int k = 0; k < 10; k++) mr[k] = __ldcg(p + k * 640);
    }

    int bit0 = lane & 1, bit1 = (lane >> 1) & 1, bit2 = (lane >> 2) & 1;
    int j8 = lane & 7;

    for (int step = 0; step < NSTEP; ++step) {
        int pb = step & 1, nb = 1 - pb;
        int d = sg[step] & 3;
        int zn = sg[step + 1] >> 2;                // sentinel makes last lookahead safe
        int dn = sg[step + 1] & 3;

        // si_prev from last step's totals (buffer nb holds s_{step-1}; init => 1 at step 0)
        float4 q0 = *(const float4*)&redp[nb][0];
        float4 q1 = *(const float4*)&redp[nb][4];
        float4 q2 = *(const float4*)&redp[nb][8];
        float4 q3 = *(const float4*)&redp[nb][12];
        float4 q4 = *(const float4*)&redp[nb][16];
        float tot = ((q0.x + q0.y) + (q0.z + q0.w)) + ((q1.x + q1.y) + (q1.z + q1.w))
                  + ((q2.x + q2.y) + (q2.z + q2.w)) + ((q3.x + q3.y) + (q3.z + q3.w))
                  + ((q4.x + q4.y) + (q4.z + q4.w));
        float si = __frcp_rn(tot);
        if (tid == 0) {                            // Kahan log of s_{step-1} (log(1)=0 at step 0)
            float y = logf(tot) - lcomp;
            float t2 = llf + y;
            lcomp = (t2 - llf) - y;
            llf = t2;
        }

        // prefetch fold (this step) + next row-scales (own 2 states; exact bias-cancel rs)
        float2 fo  = *(const float2*)&g_BmT[d][16 * w + 2 * j8];
        float2 rsv = *(const float2*)&g_rs[(size_t)(zn * 4 + dn) * SP + 16 * w + 2 * j8];

        // ---- FMA phase: warp w, cols 16w..16w+15; lane rows lane+32k (reads ah2[pb]) ----
        __half2 a0 = __floats2half2_rn(0.f, 0.f);
        __half2 a1 = a0, a2 = a0, a3 = a0, a4 = a0, a5 = a0, a6 = a0, a7 = a0;
        #pragma unroll
        for (int k = 0; k < 10; k++) {
            __half2 av = ah2[pb][lane + 32 * k];
            a0 = __hfma2(av, u2h(__byte_perm(mr[k].x, 0, 0x1404)), a0);
            a1 = __hfma2(av, u2h(__byte_perm(mr[k].x, 0, 0x3424)), a1);
            a2 = __hfma2(av, u2h(__byte_perm(mr[k].y, 0, 0x1404)), a2);
            a3 = __hfma2(av, u2h(__byte_perm(mr[k].y, 0, 0x3424)), a3);
            a4 = __hfma2(av, u2h(__byte_perm(mr[k].z, 0, 0x1404)), a4);
            a5 = __hfma2(av, u2h(__byte_perm(mr[k].z, 0, 0x3424)), a5);
            a6 = __hfma2(av, u2h(__byte_perm(mr[k].w, 0, 0x1404)), a6);
            a7 = __hfma2(av, u2h(__byte_perm(mr[k].w, 0, 0x3424)), a7);
        }

        // ---- issue next step's matrix loads (mr regs now free) ----
        {
            const uint4* p = (const uint4*)(g_S + (size_t)zn * SPSP) + tid;
            #pragma unroll
            for (int k = 0; k < 10; k++) mr[k] = __ldcg(p + k * 640);
        }

        // ---- in-warp reg-halving reduce: all lanes end with col pair j = lane&7 ----
        uint32_t h0 = h2u(a0), h1 = h2u(a1), h2v = h2u(a2), h3 = h2u(a3);
        uint32_t h4 = h2u(a4), h5 = h2u(a5), h6 = h2u(a6), h7 = h2u(a7);
        {
            uint32_t g0 = bit0 ? h0 : h1, g1 = bit0 ? h2v : h3;
            uint32_t g2 = bit0 ? h4 : h5, g3 = bit0 ? h6 : h7;
            uint32_t r0 = __shfl_xor_sync(0xffffffffu, g0, 1);
            uint32_t r1 = __shfl_xor_sync(0xffffffffu, g1, 1);
            uint32_t r2 = __shfl_xor_sync(0xffffffffu, g2, 1);
            uint32_t r3 = __shfl_xor_sync(0xffffffffu, g3, 1);
            h0 = hadd2u(bit0 ? h1 : h0, r0);
            h1 = hadd2u(bit0 ? h3 : h2v, r1);
            h2v = hadd2u(bit0 ? h5 : h4, r2);
            h3 = hadd2u(bit0 ? h7 : h6, r3);
        }
        {
            uint32_t g0 = bit1 ? h0 : h1, g1 = bit1 ? h2v : h3;
            uint32_t r0 = __shfl_xor_sync(0xffffffffu, g0, 2);
            uint32_t r1 = __shfl_xor_sync(0xffffffffu, g1, 2);
            h0 = hadd2u(bit1 ? h1 : h0, r0);
            h1 = hadd2u(bit1 ? h3 : h2v, r1);
        }
        {
            uint32_t g0 = bit2 ? h0 : h1;
            uint32_t r0 = __shfl_xor_sync(0xffffffffu, g0, 4);
            h0 = hadd2u(bit2 ? h1 : h0, r0);
        }
        h0 = hadd2u(h0, __shfl_xor_sync(0xffffffffu, h0, 8));
        h0 = hadd2u(h0, __shfl_xor_sync(0xffffffffu, h0, 16));

        // lanes 0-7: finish own 2 states — apply fold + si_prev, write ah2[nb] slice
        float p = 0.f;
        if (lane < 8) {
            float2 f2 = __half22float2(u2h(h0));
            float v0 = f2.x * fo.x * si, v1 = f2.y * fo.y * si;
            float b0 = v0 * rsv.x, b1 = v1 * rsv.y;     // next alpha, un-si'd (deferred)
            uint2 packed;
            packed.x = h2u(__floats2half2_rn(b0, b0));
            packed.y = h2u(__floats2half2_rn(b1, b1));
            *(uint2*)&ah2[nb][16 * w + 2 * j8] = packed;
            p = v0 + v1;                                 // contribution to s_step
        }
        p += __shfl_xor_sync(0xffffffffu, p, 1);
        p += __shfl_xor_sync(0xffffffffu, p, 2);
        p += __shfl_xor_sync(0xffffffffu, p, 4);
        if (lane == 0) redp[pb][w] = p;                  // publish s_step partial

        BAR_SYNC(1, 640);                                // the ONLY barrier per step
    }
    __syncthreads();
    if (tid == 0) {
        int fb = (NSTEP - 1) & 1;                        // buffer holding s_{NSTEP-1}
        float tot = 0.f;
        #pragma unroll
        for (int q = 0; q < 20; q++) tot += redp[fb][q];
        llf += logf(tot);
        out[b] = (float)((double)llf - (double)NSTEP * LOG_SCALE_D);
    }
}

// ---------------- launch ----------------
extern "C" void kernel_launch(void* const* d_in, const int* in_sizes, int n_in,
                              void* d_out, int out_size) {
    const float* inputs = (const float*)d_in[0];
    const float* initk  = (const float*)d_in[1];
    const float* transk = (const float*)d_in[2];
    const float* emisk  = (const float*)d_in[3];
    float* out = (float*)d_out;

    k_setup<<<1, 512>>>(initk, emisk);
    k_softA<<<NS, 320>>>(transk);
    k_gram<<<NB, 256>>>(inputs);
    k_gemm_h<<<dim3(5, 5, 4), 256>>>(0);     // Q_a
    k_gemm_h<<<dim3(5, 5, 16), 256>>>(1);    // U_cd
    k_gemm_h<<<dim3(5, 5, 256), 256>>>(2);   // M_abcd
    k_quant<<<dim3(40, 256), 256>>>();
    k_chain<<<NB, 640>>>(out);
}

// round 15
// speedup vs baseline: 1.1263x; 1.0663x over previous
#include <cuda_runtime.h>
#include <cuda_fp16.h>
#include <cuda_fp8.h>
#include <mma.h>
#include <math.h>
#include <stdint.h>

using namespace nvcuda;

#define NS 305
#define SP 320
#define SPSP (SP * SP)
#define NB 64
#define NT 4096
#define NSTEP 819            // 5-gram supersteps: 1 + 5*819 = 4096 exactly
#define NMAT 256             // 4^4 composite matrices
#define LOG_SCALE_D 8.317766166719343   // log(4096)

// ---------------- device globals (zero-initialized) ----------------
__device__ float g_I[SP];
__device__ __align__(16) float g_BmT[4][SP];              // BmT[a][s] = Bm[s][a]
__device__ __align__(16) __half g_A16[SPSP];              // softmax(A), fp16
__device__ __align__(16) __half g_Q16[4][SPSP];           // Q_a = (A Da) A
__device__ __align__(16) __half g_U16[16][SPSP];          // U_cd = (Q_c Dd) A
__device__ __align__(16) __half g_M16[(size_t)NMAT * SPSP];  // M_abcd = (Q_a Db) U_cd
// e5m2 SINGLE copy (26 MB, L2-resident), 8-col BLOCKED layout (R10):
// byte (r,c) at ((r>>5)*40 + (c>>3))*256 + (r&31)*8 + (c&7)
__device__ __align__(16) unsigned char g_S[(size_t)NMAT * SPSP];
// rs[(z*4+d)*SP + r] = 4096 * (sum_j BmT[d][j]*M[z][r][j]) / (sum_j BmT[d][j]*dec(S[z][r][j]))
// exact per-(z,d,row) quantization-bias cancellation folded with the 4096 scale
__device__ __align__(16) float g_rs[NMAT * 4 * SP];
__device__ unsigned short g_gram[NB * NSTEP];             // (z<<2)|fold, z in 0..255
__device__ unsigned char g_o0[NB];

__device__ __forceinline__ float warpSum(float x) {
    #pragma unroll
    for (int o = 16; o; o >>= 1) x += __shfl_down_sync(0xffffffffu, x, o);
    return x;
}
__device__ __forceinline__ float warpSumAll(float x) {
    #pragma unroll
    for (int o = 16; o; o >>= 1) x += __shfl_xor_sync(0xffffffffu, x, o);
    return x;
}
__device__ __forceinline__ float warpMax(float x) {
    #pragma unroll
    for (int o = 16; o; o >>= 1) x = fmaxf(x, __shfl_down_sync(0xffffffffu, x, o));
    return x;
}
__device__ __forceinline__ float warpMaxAll(float x) {
    #pragma unroll
    for (int o = 16; o; o >>= 1) x = fmaxf(x, __shfl_xor_sync(0xffffffffu, x, o));
    return x;
}
__device__ __forceinline__ __half2 u2h(uint32_t u) { return *reinterpret_cast<__half2*>(&u); }
__device__ __forceinline__ uint32_t h2u(__half2 h) { return *reinterpret_cast<uint32_t*>(&h); }
__device__ __forceinline__ uint32_t hadd2u(uint32_t a, uint32_t b) {
    return h2u(__hadd2(u2h(a), u2h(b)));
}
__device__ __forceinline__ uint32_t s2u(const void* p) {
    uint32_t a;
    asm("{ .reg .u64 t; cvta.to.shared.u64 t, %1; cvt.u32.u64 %0, t; }" : "=r"(a) : "l"(p));
    return a;
}

// ---------------- setup: I softmax + emission softmax ----------------
__global__ void k_setup(const float* __restrict__ initk, const float* __restrict__ emisk) {
    __shared__ float red[16];
    __shared__ float bval;
    int tid = threadIdx.x, wid = tid >> 5, lane = tid & 31;
    const int nw = 16;
    float v = (tid < NS) ? initk[tid] : -1e30f;
    float m = warpMax(v);
    if (lane == 0) red[wid] = m;
    __syncthreads();
    if (tid == 0) { float mm = -1e30f; for (int w = 0; w < nw; w++) mm = fmaxf(mm, red[w]); bval = mm; }
    __syncthreads();
    m = bval;
    float e = (tid < NS) ? expf(v - m) : 0.f;
    float s = warpSum(e);
    __syncthreads();
    if (lane == 0) red[wid] = s;
    __syncthreads();
    if (tid == 0) { float ss = 0.f; for (int w = 0; w < nw; w++) ss += red[w]; bval = ss; }
    __syncthreads();
    if (tid < NS) g_I[tid] = e / bval;

    if (tid < NS) {
        float x0 = emisk[tid * 4 + 0], x1 = emisk[tid * 4 + 1];
        float x2 = emisk[tid * 4 + 2], x3 = emisk[tid * 4 + 3];
        float mm = fmaxf(fmaxf(x0, x1), fmaxf(x2, x3));
        float e0 = expf(x0 - mm), e1 = expf(x1 - mm), e2 = expf(x2 - mm), e3 = expf(x3 - mm);
        float inv = 1.f / (e0 + e1 + e2 + e3);
        g_BmT[0][tid] = e0 * inv; g_BmT[1][tid] = e1 * inv;
        g_BmT[2][tid] = e2 * inv; g_BmT[3][tid] = e3 * inv;
    }
}

// ---------------- softmax rows of transition -> A16 ----------------
__global__ void k_softA(const float* __restrict__ trans) {
    __shared__ float red[10];
    __shared__ float bval;
    int r = blockIdx.x, tid = threadIdx.x;
    int wid = tid >> 5, lane = tid & 31;
    float v = (tid < NS) ? trans[r * NS + tid] : -1e30f;
    float m = warpMax(v);
    if (lane == 0) red[wid] = m;
    __syncthreads();
    if (tid == 0) { float mm = -1e30f; for (int w = 0; w < 10; w++) mm = fmaxf(mm, red[w]); bval = mm; }
    __syncthreads();
    m = bval;
    float e = (tid < NS) ? expf(v - m) : 0.f;
    float s = warpSum(e);
    __syncthreads();
    if (lane == 0) red[wid] = s;
    __syncthreads();
    if (tid == 0) { float ss = 0.f; for (int w = 0; w < 10; w++) ss += red[w]; bval = ss; }
    __syncthreads();
    if (tid < NS) g_A16[r * SP + tid] = __float2half_rn(e / bval);
}

// ---------------- observation -> 5-gram indices ----------------
__global__ void k_gram(const float* __restrict__ inputs) {
    int b = blockIdx.x;
    const float* inb = inputs + (size_t)b * NT * 4;
    for (int tau = threadIdx.x; tau < NSTEP; tau += blockDim.x) {
        int t0 = 1 + 5 * tau;
        unsigned g = 0;
        #pragma unroll
        for (int k = 0; k < 5; k++) {
            const float* p = inb + (size_t)(t0 + k) * 4;
            float fi = p[1] + 2.f * p[2] + 3.f * p[3];   // exact argmax of one-hot
            g = (g << 2) | (unsigned)(fi + 0.5f);
        }
        g_gram[b * NSTEP + tau] = (unsigned short)g;      // z = g>>2 (8b), fold = g&3
    }
    if (threadIdx.x == 0) {
        const float* p = inb;
        g_o0[b] = (unsigned char)(p[1] + 2.f * p[2] + 3.f * p[3] + 0.5f);
    }
}

// ---------------- wmma fp16 GEMM: C = (L * diag(sc)) @ R, all [320,320] half ----------------
// mode 0: Q_z = (A*Dz)@A (z<4); mode 1: U_z = (Q_{z>>2}*D_{z&3})@A (z<16);
// mode 2: M_z = (Q_{z>>6}*D_{(z>>4)&3})@U_{z&15} (z<256)
__global__ void __launch_bounds__(256) k_gemm_h(int mode) {
    int z = blockIdx.z;
    const __half *Lp, *Rp;
    const float* sc;
    __half* outp;
    if (mode == 0)      { Lp = g_A16;        sc = g_BmT[z];           Rp = g_A16;        outp = g_Q16[z]; }
    else if (mode == 1) { Lp = g_Q16[z >> 2]; sc = g_BmT[z & 3];      Rp = g_A16;        outp = g_U16[z]; }
    else                { Lp = g_Q16[z >> 6]; sc = g_BmT[(z >> 4) & 3]; Rp = g_U16[z & 15]; outp = g_M16 + (size_t)z * SPSP; }
    int m0 = blockIdx.y * 64, n0 = blockIdx.x * 64;

    __shared__ __align__(16) __half As[64][72];
    __shared__ __align__(16) __half Bs[64][72];
    __shared__ __align__(16) float Cs[64][68];

    int tid = threadIdx.x;
    int w = tid >> 5;
    int wm = w & 3, wn = w >> 2;                 // 4 M-blocks x 2 N-blocks (16x32 per warp)
    int lr = tid >> 2, lc = (tid & 3) * 16;

    wmma::fragment<wmma::accumulator, 16, 16, 16, float> cf[2];
    wmma::fill_fragment(cf[0], 0.f);
    wmma::fill_fragment(cf[1], 0.f);

    for (int k0 = 0; k0 < SP; k0 += 64) {
        #pragma unroll
        for (int j = 0; j < 16; j += 2) {
            __half2 lv = *(const __half2*)&Lp[(size_t)(m0 + lr) * SP + k0 + lc + j];
            float2 sv = *(const float2*)&sc[k0 + lc + j];
            float2 lf = __half22float2(lv);
            *(__half2*)&As[lr][lc + j] = __floats2half2_rn(lf.x * sv.x, lf.y * sv.y);
            *(__half2*)&Bs[lr][lc + j] = *(const __half2*)&Rp[(size_t)(k0 + lr) * SP + n0 + lc + j];
        }
        __syncthreads();
        #pragma unroll
        for (int kk = 0; kk < 4; kk++) {
            wmma::fragment<wmma::matrix_a, 16, 16, 16, __half, wmma::row_major> af;
            wmma::load_matrix_sync(af, &As[wm * 16][kk * 16], 72);
            #pragma unroll
            for (int nn = 0; nn < 2; nn++) {
                wmma::fragment<wmma::matrix_b, 16, 16, 16, __half, wmma::row_major> bf;
                wmma::load_matrix_sync(bf, &Bs[kk * 16][wn * 32 + nn * 16], 72);
                wmma::mma_sync(cf[nn], af, bf, cf[nn]);
            }
        }
        __syncthreads();
    }
    wmma::store_matrix_sync(&Cs[wm * 16][wn * 32 + 0], cf[0], 68, wmma::mem_row_major);
    wmma::store_matrix_sync(&Cs[wm * 16][wn * 32 + 16], cf[1], 68, wmma::mem_row_major);
    __syncthreads();
    #pragma unroll
    for (int j = 0; j < 16; j++)
        outp[(size_t)(m0 + lr) * SP + n0 + lc + j] = __float2half_rn(Cs[lr][lc + j]);
}

// ---------------- quantize M to e5m2 (single copy, 8-col blocked) + exact corrections ----
// grid (40, 256), block 256 (8 warps; warp handles row blockIdx.x*8+warp).
__global__ void k_quant() {
    int z = blockIdx.y;
    int warp = threadIdx.x >> 5, lane = threadIdx.x & 31;
    int r = blockIdx.x * 8 + warp;
    const __half* row = g_M16 + (size_t)z * SPSP + (size_t)r * SP;

    float vv[10];
    float mx = 0.f;
    #pragma unroll
    for (int i = 0; i < 10; i++) { vv[i] = __half2float(row[lane + 32 * i]); mx = fmaxf(mx, vv[i]); }
    mx = warpMaxAll(mx);
    float q = (mx > 0.f) ? 384.f / mx : 1.f;
    unsigned char* dst = g_S + (size_t)z * SPSP;
    int rk = r >> 5, rL = r & 31;

    float dec[10];
    #pragma unroll
    for (int i = 0; i < 10; i++) {
        int col = lane + 32 * i;
        unsigned char byte =
            (unsigned char)__nv_cvt_float_to_fp8(vv[i] * q, __NV_SATFINITE, __NV_E5M2);
        // 8-col blocked: ((rk*40 + (col>>3))*32 + rL)*8 + (col&7)
        dst[(((rk * 40 + (col >> 3)) * 32 + rL) << 3) + (col & 7)] = byte;
        // decode exactly as the chain does: e5m2 -> f16 is byte<<8 (bit-exact)
        dec[i] = __half2float(__ushort_as_half((unsigned short)(byte << 8)));
    }

    // fold-weighted true & quantized row sums for each fold d -> exact bias cancel
    #pragma unroll
    for (int d = 0; d < 4; d++) {
        float st = 0.f, sq = 0.f;
        #pragma unroll
        for (int i = 0; i < 10; i++) {
            float bm = g_BmT[d][lane + 32 * i];
            st = fmaf(bm, vv[i], st);
            sq = fmaf(bm, dec[i], sq);
        }
        st = warpSumAll(st);
        sq = warpSumAll(sq);
        if (lane == 0)
            g_rs[(z * 4 + d) * SP + r] = (sq > 0.f) ? 4096.f * st / sq : 0.f;
    }
}

// ---------------- chain: 2-CTA cluster per batch (R10 verbatim), single-copy + exact rs ----
// CTA rank owns cols [160*rank,160*rank+160); warp w owns 8 cols; lane = row-class
// (rows lane+32k). One mbarrier phase/step (arrives 640 local + 80 remote = 720).
// Deferred-si; Kahan float log on rank0/tid0. rs indexed by (z_{t+1}, d_{t+1}).
__global__ void __launch_bounds__(640, 1) __cluster_dims__(2, 1, 1)
k_chain(float* __restrict__ out) {
    int tid = threadIdx.x;
    int b = blockIdx.x >> 1;
    uint32_t rank;
    asm("mov.u32 %0, %%cluster_ctarank;" : "=r"(rank));
    int peer = 1 - (int)rank;

    __shared__ __half2 ah2[2][SP];
    __shared__ __align__(16) float redp[2][48];    // slots 0..39 used (rank*20 + w)
    __shared__ unsigned short sg[NSTEP + 1];
    __shared__ __align__(8) uint64_t mbar;
    __shared__ float pr[20];
    __shared__ float psinv;
    __shared__ float af[SP];

    int lane = tid & 31, w = tid >> 5;
    uint32_t mbarA = s2u(&mbar);

    for (int i = tid; i < NSTEP; i += 640) sg[i] = g_gram[b * NSTEP + i];
    int o0 = g_o0[b];
    if (tid == 0) sg[NSTEP] = 0;                   // sentinel for step+1 lookahead
    if (tid < 48) { redp[0][tid] = 0.f; redp[1][tid] = (tid == 0) ? 1.f : 0.f; }
    if (tid == 0)
        asm volatile("mbarrier.init.shared.b64 [%0], %1;" :: "r"(mbarA), "r"(720) : "memory");
    __syncthreads();
    asm volatile("barrier.cluster.arrive.aligned;" ::: "memory");
    asm volatile("barrier.cluster.wait.aligned;" ::: "memory");

    int z0 = sg[0] >> 2, d0 = sg[0] & 3;

    // ---- prologue: both CTAs build the FULL normalized alpha0, scaled by rs(z0,d0) ----
    float llf = 0.f, lcomp = 0.f;
    {
        float v0p = (tid < SP) ? g_I[tid] * g_BmT[o0][tid] : 0.f;
        float wsum = warpSum(v0p);
        if (lane == 0) pr[w] = wsum;
        __syncthreads();
        if (tid == 0) {
            float x = 0.f;
            #pragma unroll
            for (int q = 0; q < 20; q++) x += pr[q];
            psinv = 1.f / x;
            pr[0] = x;
        }
        __syncthreads();
        llf = logf(pr[0]);
        if (tid < SP) af[tid] = v0p * psinv;
        __syncthreads();
        if (tid < 160) {
            float2 rsv = *(const float2*)&g_rs[(z0 * 4 + d0) * SP + 2 * tid];
            float a0 = af[2 * tid] * rsv.x, a1 = af[2 * tid + 1] * rsv.y;
            ah2[0][2 * tid]     = __floats2half2_rn(a0, a0);
            ah2[0][2 * tid + 1] = __floats2half2_rn(a1, a1);
        }
        __syncthreads();
    }

    int cb = (int)rank * 20 + w;                   // 8-col block index owned by this warp
    int gcol = (int)rank * 160 + 8 * w + 2 * (lane & 3);
    int slot = (int)rank * 20 + w;
    int bit0 = lane & 1, bit1 = (lane >> 1) & 1;

    // ---- preload mr for step 0 ----
    uint2 mr[10];
    {
        const uint2* base = (const uint2*)(g_S + (size_t)z0 * SPSP);
        #pragma unroll
        for (int k = 0; k < 10; k++) mr[k] = __ldcg(base + (k * 40 + cb) * 32 + lane);
    }

    for (int step = 0; step < NSTEP; ++step) {
        int pb = step & 1, nb = 1 - pb;
        int d = sg[step] & 3;
        int zn = sg[step + 1] >> 2;                // sentinel makes last lookahead safe
        int dn = sg[step + 1] & 3;

        // si_prev from last step's 40 global partials
        float tot = 0.f;
        #pragma unroll
        for (int q = 0; q < 10; q++) {
            float4 t = *(const float4*)&redp[nb][4 * q];
            tot += (t.x + t.y) + (t.z + t.w);
        }
        float si = __frcp_rn(tot);
        if (rank == 0 && tid == 0) {               // Kahan log of s_{step-1} (log(1)=0 at step 0)
            float y = logf(tot) - lcomp;
            float t2 = llf + y;
            lcomp = (t2 - llf) - y;
            llf = t2;
        }
        float2 fo  = *(const float2*)&g_BmT[d][gcol];
        float2 rsv = *(const float2*)&g_rs[(size_t)(zn * 4 + dn) * SP + gcol];

        // ---- FMA phase: 8 cols, rows lane+32k ----
        __half2 a0 = __floats2half2_rn(0.f, 0.f);
        __half2 a1 = a0, a2 = a0, a3 = a0;
        #pragma unroll
        for (int k = 0; k < 10; k++) {
            __half2 av = ah2[pb][lane + 32 * k];
            a0 = __hfma2(av, u2h(__byte_perm(mr[k].x, 0, 0x1404)), a0);
            a1 = __hfma2(av, u2h(__byte_perm(mr[k].x, 0, 0x3424)), a1);
            a2 = __hfma2(av, u2h(__byte_perm(mr[k].y, 0, 0x1404)), a2);
            a3 = __hfma2(av, u2h(__byte_perm(mr[k].y, 0, 0x3424)), a3);
        }

        // ---- in-warp reduce: lane ends holding col-pair (lane&3) total ----
        uint32_t h0 = h2u(a0), h1 = h2u(a1), h2v = h2u(a2), h3 = h2u(a3);
        {
            uint32_t g0 = bit0 ? h0 : h1, g1 = bit0 ? h2v : h3;
            uint32_t r0 = __shfl_xor_sync(0xffffffffu, g0, 1);
            uint32_t r1 = __shfl_xor_sync(0xffffffffu, g1, 1);
            h0 = hadd2u(bit0 ? h1 : h0, r0);
            h1 = hadd2u(bit0 ? h3 : h2v, r1);
        }
        {
            uint32_t g0 = bit1 ? h0 : h1;
            uint32_t r0 = __shfl_xor_sync(0xffffffffu, g0, 2);
            h0 = hadd2u(bit1 ? h1 : h0, r0);
        }
        h0 = hadd2u(h0, __shfl_xor_sync(0xffffffffu, h0, 4));
        h0 = hadd2u(h0, __shfl_xor_sync(0xffffffffu, h0, 8));
        h0 = hadd2u(h0, __shfl_xor_sync(0xffffffffu, h0, 16));

        // ---- lanes 0-3: finish own 2 cols, write local + remote alpha ----
        float p = 0.f;
        if (lane < 4) {
            float2 f2 = __half22float2(u2h(h0));
            float v0 = f2.x * fo.x * si, v1 = f2.y * fo.y * si;
            float b0 = v0 * rsv.x, b1 = v1 * rsv.y;   // next alpha, un-si'd (deferred)
            uint32_t pkx = h2u(__floats2half2_rn(b0, b0));
            uint32_t pky = h2u(__floats2half2_rn(b1, b1));
            *(uint2*)&ah2[nb][gcol] = make_uint2(pkx, pky);
            uint64_t vv = ((uint64_t)pky << 32) | pkx;
            uint32_t la = s2u(&ah2[nb][gcol]);
            asm volatile(
                "{ .reg .b32 ra; mapa.shared::cluster.u32 ra, %0, %1;"
                "  st.shared::cluster.b64 [ra], %2; }"
                :: "r"(la), "r"(peer), "l"(vv) : "memory");
            p = v0 + v1;
        }
        p += __shfl_xor_sync(0xffffffffu, p, 1);
        p += __shfl_xor_sync(0xffffffffu, p, 2);
        if (lane == 0) {
            redp[pb][slot] = p;
            uint32_t la = s2u(&redp[pb][slot]);
            asm volatile(
                "{ .reg .b32 ra; mapa.shared::cluster.u32 ra, %0, %1;"
                "  st.shared::cluster.b32 [ra], %2; }"
                :: "r"(la), "r"(peer), "f"(p) : "memory");
        }
        if (lane < 4) {
            asm volatile(
                "{ .reg .b32 ra; mapa.shared::cluster.u32 ra, %0, %1;"
                "  mbarrier.arrive.shared::cluster.b64 _, [ra]; }"
                :: "r"(mbarA), "r"(peer) : "memory");
        }
        asm volatile("mbarrier.arrive.shared.b64 _, [%0];" :: "r"(mbarA) : "memory");

        // ---- issue next step's mr loads while the barrier settles ----
        {
            const uint2* base = (const uint2*)(g_S + (size_t)zn * SPSP);
            #pragma unroll
            for (int k = 0; k < 10; k++) mr[k] = __ldcg(base + (k * 40 + cb) * 32 + lane);
        }

        // ---- wait for phase completion (720 arrives), cluster-acquire ----
        {
            uint32_t parity = (uint32_t)(step & 1);
            uint32_t done;
            asm volatile(
                "{ .reg .pred P;"
                "  mbarrier.try_wait.parity.acquire.cluster.shared::cta.b64 P, [%1], %2;"
                "  selp.b32 %0, 1, 0, P; }"
                : "=r"(done) : "r"(mbarA), "r"(parity) : "memory");
            if (!done) {
                asm volatile(
                    "{ .reg .pred P;"
                    "WL_%=:"
                    "  mbarrier.try_wait.parity.acquire.cluster.shared::cta.b64 P, [%0], %1, 0x989680;"
                    "  @P bra WD_%=;"
                    "  bra WL_%=;"
                    "WD_%=: }"
                    :: "r"(mbarA), "r"(parity) : "memory");
            }
        }
    }

    if (rank == 0 && tid == 0) {
        int fb = (NSTEP - 1) & 1;                    // buffer holding s_{NSTEP-1}
        float tot = 0.f;
        #pragma unroll
        for (int q = 0; q < 40; q++) tot += redp[fb][q];
        llf += logf(tot);
        out[b] = (float)((double)llf - (double)NSTEP * LOG_SCALE_D);
    }
}

// ---------------- launch ----------------
extern "C" void kernel_launch(void* const* d_in, const int* in_sizes, int n_in,
                              void* d_out, int out_size) {
    const float* inputs = (const float*)d_in[0];
    const float* initk  = (const float*)d_in[1];
    const float* transk = (const float*)d_in[2];
    const float* emisk  = (const float*)d_in[3];
    float* out = (float*)d_out;

    k_setup<<<1, 512>>>(initk, emisk);
    k_softA<<<NS, 320>>>(transk);
    k_gram<<<NB, 256>>>(inputs);
    k_gemm_h<<<dim3(5, 5, 4), 256>>>(0);     // Q_a
    k_gemm_h<<<dim3(5, 5, 16), 256>>>(1);    // U_cd
    k_gemm_h<<<dim3(5, 5, 256), 256>>>(2);   // M_abcd
    k_quant<<<dim3(40, 256), 256>>>();
    k_chain<<<NB * 2, 640>>>(out);
}

// round 16
// speedup vs baseline: 1.2877x; 1.1433x over previous
#include <cuda_runtime.h>
#include <cuda_fp16.h>
#include <cuda_fp8.h>
#include <mma.h>
#include <math.h>
#include <stdint.h>

using namespace nvcuda;

#define NS 305
#define SP 320
#define SPSP (SP * SP)
#define NB 64
#define NT 4096
#define NSTEP 819            // 5-gram supersteps: 1 + 5*819 = 4096 exactly
#define NMAT 256             // 4^4 composite matrices
#define LOG_SCALE_D 8.317766166719343   // log(4096)

// ---------------- device globals (zero-initialized) ----------------
__device__ float g_I[SP];
__device__ __align__(16) float g_BmT[4][SP];              // BmT[a][s] = Bm[s][a]
__device__ __align__(16) __half g_A16[SPSP];              // softmax(A), fp16
__device__ __align__(16) __half g_Q16[4][SPSP];           // Q_a = (A Da) A
__device__ __align__(16) __half g_U16[16][SPSP];          // U_cd = (Q_c Dd) A
__device__ __align__(16) __half g_M16[(size_t)NMAT * SPSP];  // M_abcd = (Q_a Db) U_cd
// e5m2 SINGLE copy (26 MB), 8-col BLOCKED layout:
// byte (r,c) at ((r>>5)*40 + (c>>3))*256 + (r&31)*8 + (c&7)
__device__ __align__(16) unsigned char g_S[(size_t)NMAT * SPSP];
// rs[(z*4+d)*SP + r] = 4096 * (sum_j BmT[d][j]*M[z][r][j]) / (sum_j BmT[d][j]*dec(S[z][r][j]))
__device__ __align__(16) float g_rs[NMAT * 4 * SP];
__device__ unsigned short g_gram[NB * NSTEP];             // (z<<2)|fold
__device__ unsigned char g_o0[NB];

__device__ __forceinline__ float warpSum(float x) {
    #pragma unroll
    for (int o = 16; o; o >>= 1) x += __shfl_down_sync(0xffffffffu, x, o);
    return x;
}
__device__ __forceinline__ float warpSumAll(float x) {
    #pragma unroll
    for (int o = 16; o; o >>= 1) x += __shfl_xor_sync(0xffffffffu, x, o);
    return x;
}
__device__ __forceinline__ float warpMax(float x) {
    #pragma unroll
    for (int o = 16; o; o >>= 1) x = fmaxf(x, __shfl_down_sync(0xffffffffu, x, o));
    return x;
}
__device__ __forceinline__ float warpMaxAll(float x) {
    #pragma unroll
    for (int o = 16; o; o >>= 1) x = fmaxf(x, __shfl_xor_sync(0xffffffffu, x, o));
    return x;
}
__device__ __forceinline__ __half2 u2h(uint32_t u) { return *reinterpret_cast<__half2*>(&u); }
__device__ __forceinline__ uint32_t h2u(__half2 h) { return *reinterpret_cast<uint32_t*>(&h); }
__device__ __forceinline__ uint32_t hadd2u(uint32_t a, uint32_t b) {
    return h2u(__hadd2(u2h(a), u2h(b)));
}
__device__ __forceinline__ uint32_t s2u(const void* p) {
    uint32_t a;
    asm("{ .reg .u64 t; cvta.to.shared.u64 t, %1; cvt.u32.u64 %0, t; }" : "=r"(a) : "l"(p));
    return a;
}

// ---------------- setup: I softmax + emission softmax ----------------
__global__ void k_setup(const float* __restrict__ initk, const float* __restrict__ emisk) {
    __shared__ float red[16];
    __shared__ float bval;
    int tid = threadIdx.x, wid = tid >> 5, lane = tid & 31;
    const int nw = 16;
    float v = (tid < NS) ? initk[tid] : -1e30f;
    float m = warpMax(v);
    if (lane == 0) red[wid] = m;
    __syncthreads();
    if (tid == 0) { float mm = -1e30f; for (int w = 0; w < nw; w++) mm = fmaxf(mm, red[w]); bval = mm; }
    __syncthreads();
    m = bval;
    float e = (tid < NS) ? expf(v - m) : 0.f;
    float s = warpSum(e);
    __syncthreads();
    if (lane == 0) red[wid] = s;
    __syncthreads();
    if (tid == 0) { float ss = 0.f; for (int w = 0; w < nw; w++) ss += red[w]; bval = ss; }
    __syncthreads();
    if (tid < NS) g_I[tid] = e / bval;

    if (tid < NS) {
        float x0 = emisk[tid * 4 + 0], x1 = emisk[tid * 4 + 1];
        float x2 = emisk[tid * 4 + 2], x3 = emisk[tid * 4 + 3];
        float mm = fmaxf(fmaxf(x0, x1), fmaxf(x2, x3));
        float e0 = expf(x0 - mm), e1 = expf(x1 - mm), e2 = expf(x2 - mm), e3 = expf(x3 - mm);
        float inv = 1.f / (e0 + e1 + e2 + e3);
        g_BmT[0][tid] = e0 * inv; g_BmT[1][tid] = e1 * inv;
        g_BmT[2][tid] = e2 * inv; g_BmT[3][tid] = e3 * inv;
    }
}

// ---------------- softmax rows of transition -> A16 ----------------
__global__ void k_softA(const float* __restrict__ trans) {
    __shared__ float red[10];
    __shared__ float bval;
    int r = blockIdx.x, tid = threadIdx.x;
    int wid = tid >> 5, lane = tid & 31;
    float v = (tid < NS) ? trans[r * NS + tid] : -1e30f;
    float m = warpMax(v);
    if (lane == 0) red[wid] = m;
    __syncthreads();
    if (tid == 0) { float mm = -1e30f; for (int w = 0; w < 10; w++) mm = fmaxf(mm, red[w]); bval = mm; }
    __syncthreads();
    m = bval;
    float e = (tid < NS) ? expf(v - m) : 0.f;
    float s = warpSum(e);
    __syncthreads();
    if (lane == 0) red[wid] = s;
    __syncthreads();
    if (tid == 0) { float ss = 0.f; for (int w = 0; w < 10; w++) ss += red[w]; bval = ss; }
    __syncthreads();
    if (tid < NS) g_A16[r * SP + tid] = __float2half_rn(e / bval);
}

// ---------------- observation -> 5-gram indices ----------------
__global__ void k_gram(const float* __restrict__ inputs) {
    int b = blockIdx.x;
    const float* inb = inputs + (size_t)b * NT * 4;
    for (int tau = threadIdx.x; tau < NSTEP; tau += blockDim.x) {
        int t0 = 1 + 5 * tau;
        unsigned g = 0;
        #pragma unroll
        for (int k = 0; k < 5; k++) {
            const float* p = inb + (size_t)(t0 + k) * 4;
            float fi = p[1] + 2.f * p[2] + 3.f * p[3];   // exact argmax of one-hot
            g = (g << 2) | (unsigned)(fi + 0.5f);
        }
        g_gram[b * NSTEP + tau] = (unsigned short)g;
    }
    if (threadIdx.x == 0) {
        const float* p = inb;
        g_o0[b] = (unsigned char)(p[1] + 2.f * p[2] + 3.f * p[3] + 0.5f);
    }
}

// ---------------- wmma fp16 GEMM, vectorized + smem-unioned ----------------
// C = (L * diag(sc)) @ R, all [320,320] half.
// mode 0: Q_z; mode 1: U_z; mode 2: M_z. Cs overlaps As/Bs (dead after mainloop).
__global__ void __launch_bounds__(256) k_gemm_h(int mode) {
    int z = blockIdx.z;
    const __half *Lp, *Rp;
    const float* sc;
    __half* outp;
    if (mode == 0)      { Lp = g_A16;        sc = g_BmT[z];           Rp = g_A16;        outp = g_Q16[z]; }
    else if (mode == 1) { Lp = g_Q16[z >> 2]; sc = g_BmT[z & 3];      Rp = g_A16;        outp = g_U16[z]; }
    else                { Lp = g_Q16[z >> 6]; sc = g_BmT[(z >> 4) & 3]; Rp = g_U16[z & 15]; outp = g_M16 + (size_t)z * SPSP; }
    int m0 = blockIdx.y * 64, n0 = blockIdx.x * 64;

    __shared__ __align__(16) char smem_buf[2 * 64 * 72 * 2];   // 18432 B
    __half (*As)[72] = (__half(*)[72])smem_buf;
    __half (*Bs)[72] = (__half(*)[72])(smem_buf + 64 * 72 * 2);
    float (*Cs)[68] = (float(*)[68])smem_buf;                  // UNION (17408 B)

    int tid = threadIdx.x;
    int w = tid >> 5;
    int wm = w & 3, wn = w >> 2;                 // 4 M-blocks x 2 N-blocks (16x32 per warp)
    int lr = tid >> 2, lc = (tid & 3) * 16;

    wmma::fragment<wmma::accumulator, 16, 16, 16, float> cf[2];
    wmma::fill_fragment(cf[0], 0.f);
    wmma::fill_fragment(cf[1], 0.f);

    for (int k0 = 0; k0 < SP; k0 += 64) {
        #pragma unroll
        for (int h = 0; h < 2; h++) {
            int c8 = lc + 8 * h;
            uint4 lv = *(const uint4*)&Lp[(size_t)(m0 + lr) * SP + k0 + c8];
            float4 s0 = *(const float4*)&sc[k0 + c8];
            float4 s1 = *(const float4*)&sc[k0 + c8 + 4];
            float2 f0 = __half22float2(u2h(lv.x));
            float2 f1 = __half22float2(u2h(lv.y));
            float2 f2 = __half22float2(u2h(lv.z));
            float2 f3 = __half22float2(u2h(lv.w));
            uint4 ov;
            ov.x = h2u(__floats2half2_rn(f0.x * s0.x, f0.y * s0.y));
            ov.y = h2u(__floats2half2_rn(f1.x * s0.z, f1.y * s0.w));
            ov.z = h2u(__floats2half2_rn(f2.x * s1.x, f2.y * s1.y));
            ov.w = h2u(__floats2half2_rn(f3.x * s1.z, f3.y * s1.w));
            *(uint4*)&As[lr][c8] = ov;
            *(uint4*)&Bs[lr][c8] = *(const uint4*)&Rp[(size_t)(k0 + lr) * SP + n0 + c8];
        }
        __syncthreads();
        #pragma unroll
        for (int kk = 0; kk < 4; kk++) {
            wmma::fragment<wmma::matrix_a, 16, 16, 16, __half, wmma::row_major> af;
            wmma::load_matrix_sync(af, &As[wm * 16][kk * 16], 72);
            #pragma unroll
            for (int nn = 0; nn < 2; nn++) {
                wmma::fragment<wmma::matrix_b, 16, 16, 16, __half, wmma::row_major> bf;
                wmma::load_matrix_sync(bf, &Bs[kk * 16][wn * 32 + nn * 16], 72);
                wmma::mma_sync(cf[nn], af, bf, cf[nn]);
            }
        }
        __syncthreads();
    }
    // As/Bs dead; Cs aliases them (post-loop __syncthreads already done)
    wmma::store_matrix_sync(&Cs[wm * 16][wn * 32 + 0], cf[0], 68, wmma::mem_row_major);
    wmma::store_matrix_sync(&Cs[wm * 16][wn * 32 + 16], cf[1], 68, wmma::mem_row_major);
    __syncthreads();
    {
        float4 c0 = *(const float4*)&Cs[lr][lc + 0];
        float4 c1 = *(const float4*)&Cs[lr][lc + 4];
        float4 c2 = *(const float4*)&Cs[lr][lc + 8];
        float4 c3 = *(const float4*)&Cs[lr][lc + 12];
        uint4 o0, o1;
        o0.x = h2u(__floats2half2_rn(c0.x, c0.y));
        o0.y = h2u(__floats2half2_rn(c0.z, c0.w));
        o0.z = h2u(__floats2half2_rn(c1.x, c1.y));
        o0.w = h2u(__floats2half2_rn(c1.z, c1.w));
        o1.x = h2u(__floats2half2_rn(c2.x, c2.y));
        o1.y = h2u(__floats2half2_rn(c2.z, c2.w));
        o1.z = h2u(__floats2half2_rn(c3.x, c3.y));
        o1.w = h2u(__floats2half2_rn(c3.z, c3.w));
        __half* op = outp + (size_t)(m0 + lr) * SP + n0 + lc;
        *(uint4*)op = o0;
        *(uint4*)(op + 8) = o1;
    }
}

// ---------------- quantize M to e5m2 + exact corrections (vectorized) ----------------
// grid (40, 256), block 256; warp handles row r = blockIdx.x*8 + warp.
// Lane covers 8-col block j=lane; lanes 0-7 also block 32+lane (40 blocks/row).
// uint4 row loads, uint2 packed-byte stores, correction sums from registers.
__global__ void k_quant() {
    int z = blockIdx.y;
    int warp = threadIdx.x >> 5, lane = threadIdx.x & 31;
    int r = blockIdx.x * 8 + warp;
    const __half* row = g_M16 + (size_t)z * SPSP + (size_t)r * SP;
    bool two = (lane < 8);
    int j0 = lane, j1 = 32 + lane;

    float f0[8], f1[8];
    {
        uint4 v = *(const uint4*)&row[8 * j0];
        float2 a = __half22float2(u2h(v.x)), b2 = __half22float2(u2h(v.y));
        float2 c = __half22float2(u2h(v.z)), e = __half22float2(u2h(v.w));
        f0[0] = a.x; f0[1] = a.y; f0[2] = b2.x; f0[3] = b2.y;
        f0[4] = c.x; f0[5] = c.y; f0[6] = e.x; f0[7] = e.y;
    }
    if (two) {
        uint4 v = *(const uint4*)&row[8 * j1];
        float2 a = __half22float2(u2h(v.x)), b2 = __half22float2(u2h(v.y));
        float2 c = __half22float2(u2h(v.z)), e = __half22float2(u2h(v.w));
        f1[0] = a.x; f1[1] = a.y; f1[2] = b2.x; f1[3] = b2.y;
        f1[4] = c.x; f1[5] = c.y; f1[6] = e.x; f1[7] = e.y;
    } else {
        #pragma unroll
        for (int i = 0; i < 8; i++) f1[i] = 0.f;
    }

    float mx = 0.f;
    #pragma unroll
    for (int i = 0; i < 8; i++) mx = fmaxf(mx, fmaxf(f0[i], f1[i]));
    mx = warpMaxAll(mx);
    float q = (mx > 0.f) ? 384.f / mx : 1.f;

    unsigned char* dst = g_S + (size_t)z * SPSP;
    int rk = r >> 5, rL = r & 31;

    float d0[8], d1[8];
    {
        uint2 pk;
        uint32_t b_ = 0;
        #pragma unroll
        for (int i = 0; i < 4; i++) {
            unsigned char byte = (unsigned char)__nv_cvt_float_to_fp8(f0[i] * q, __NV_SATFINITE, __NV_E5M2);
            d0[i] = __half2float(__ushort_as_half((unsigned short)(byte << 8)));
            b_ |= (uint32_t)byte << (8 * i);
        }
        pk.x = b_; b_ = 0;
        #pragma unroll
        for (int i = 0; i < 4; i++) {
            unsigned char byte = (unsigned char)__nv_cvt_float_to_fp8(f0[i + 4] * q, __NV_SATFINITE, __NV_E5M2);
            d0[i + 4] = __half2float(__ushort_as_half((unsigned short)(byte << 8)));
            b_ |= (uint32_t)byte << (8 * i);
        }
        pk.y = b_;
        *(uint2*)&dst[(((rk * 40 + j0) * 32 + rL) << 3)] = pk;
    }
    if (two) {
        uint2 pk;
        uint32_t b_ = 0;
        #pragma unroll
        for (int i = 0; i < 4; i++) {
            unsigned char byte = (unsigned char)__nv_cvt_float_to_fp8(f1[i] * q, __NV_SATFINITE, __NV_E5M2);
            d1[i] = __half2float(__ushort_as_half((unsigned short)(byte << 8)));
            b_ |= (uint32_t)byte << (8 * i);
        }
        pk.x = b_; b_ = 0;
        #pragma unroll
        for (int i = 0; i < 4; i++) {
            unsigned char byte = (unsigned char)__nv_cvt_float_to_fp8(f1[i + 4] * q, __NV_SATFINITE, __NV_E5M2);
            d1[i + 4] = __half2float(__ushort_as_half((unsigned short)(byte << 8)));
            b_ |= (uint32_t)byte << (8 * i);
        }
        pk.y = b_;
        *(uint2*)&dst[(((rk * 40 + j1) * 32 + rL) << 3)] = pk;
    } else {
        #pragma unroll
        for (int i = 0; i < 8; i++) d1[i] = 0.f;
    }

    // fold-weighted true & quantized row sums per d -> exact bias cancel
    #pragma unroll
    for (int d = 0; d < 4; d++) {
        float st = 0.f, sq = 0.f;
        float4 bm0a = *(const float4*)&g_BmT[d][8 * j0];
        float4 bm0b = *(const float4*)&g_BmT[d][8 * j0 + 4];
        st = fmaf(bm0a.x, f0[0], st); sq = fmaf(bm0a.x, d0[0], sq);
        st = fmaf(bm0a.y, f0[1], st); sq = fmaf(bm0a.y, d0[1], sq);
        st = fmaf(bm0a.z, f0[2], st); sq = fmaf(bm0a.z, d0[2], sq);
        st = fmaf(bm0a.w, f0[3], st); sq = fmaf(bm0a.w, d0[3], sq);
        st = fmaf(bm0b.x, f0[4], st); sq = fmaf(bm0b.x, d0[4], sq);
        st = fmaf(bm0b.y, f0[5], st); sq = fmaf(bm0b.y, d0[5], sq);
        st = fmaf(bm0b.z, f0[6], st); sq = fmaf(bm0b.z, d0[6], sq);
        st = fmaf(bm0b.w, f0[7], st); sq = fmaf(bm0b.w, d0[7], sq);
        if (two) {
            float4 bm1a = *(const float4*)&g_BmT[d][8 * j1];
            float4 bm1b = *(const float4*)&g_BmT[d][8 * j1 + 4];
            st = fmaf(bm1a.x, f1[0], st); sq = fmaf(bm1a.x, d1[0], sq);
            st = fmaf(bm1a.y, f1[1], st); sq = fmaf(bm1a.y, d1[1], sq);
            st = fmaf(bm1a.z, f1[2], st); sq = fmaf(bm1a.z, d1[2], sq);
            st = fmaf(bm1a.w, f1[3], st); sq = fmaf(bm1a.w, d1[3], sq);
            st = fmaf(bm1b.x, f1[4], st); sq = fmaf(bm1b.x, d1[4], sq);
            st = fmaf(bm1b.y, f1[5], st); sq = fmaf(bm1b.y, d1[5], sq);
            st = fmaf(bm1b.z, f1[6], st); sq = fmaf(bm1b.z, d1[6], sq);
            st = fmaf(bm1b.w, f1[7], st); sq = fmaf(bm1b.w, d1[7], sq);
        }
        st = warpSumAll(st);
        sq = warpSumAll(sq);
        if (lane == 0)
            g_rs[(z * 4 + d) * SP + r] = (sq > 0.f) ? 4096.f * st / sq : 0.f;
    }
}

// ---------------- chain: 2-CTA cluster per batch (R15 VERBATIM) ----------------
__global__ void __launch_bounds__(640, 1) __cluster_dims__(2, 1, 1)
k_chain(float* __restrict__ out) {
    int tid = threadIdx.x;
    int b = blockIdx.x >> 1;
    uint32_t rank;
    asm("mov.u32 %0, %%cluster_ctarank;" : "=r"(rank));
    int peer = 1 - (int)rank;

    __shared__ __half2 ah2[2][SP];
    __shared__ __align__(16) float redp[2][48];
    __shared__ unsigned short sg[NSTEP + 1];
    __shared__ __align__(8) uint64_t mbar;
    __shared__ float pr[20];
    __shared__ float psinv;
    __shared__ float af[SP];

    int lane = tid & 31, w = tid >> 5;
    uint32_t mbarA = s2u(&mbar);

    for (int i = tid; i < NSTEP; i += 640) sg[i] = g_gram[b * NSTEP + i];
    int o0 = g_o0[b];
    if (tid == 0) sg[NSTEP] = 0;
    if (tid < 48) { redp[0][tid] = 0.f; redp[1][tid] = (tid == 0) ? 1.f : 0.f; }
    if (tid == 0)
        asm volatile("mbarrier.init.shared.b64 [%0], %1;" :: "r"(mbarA), "r"(720) : "memory");
    __syncthreads();
    asm volatile("barrier.cluster.arrive.aligned;" ::: "memory");
    asm volatile("barrier.cluster.wait.aligned;" ::: "memory");

    int z0 = sg[0] >> 2, d0 = sg[0] & 3;

    float llf = 0.f, lcomp = 0.f;
    {
        float v0p = (tid < SP) ? g_I[tid] * g_BmT[o0][tid] : 0.f;
        float wsum = warpSum(v0p);
        if (lane == 0) pr[w] = wsum;
        __syncthreads();
        if (tid == 0) {
            float x = 0.f;
            #pragma unroll
            for (int q = 0; q < 20; q++) x += pr[q];
            psinv = 1.f / x;
            pr[0] = x;
        }
        __syncthreads();
        llf = logf(pr[0]);
        if (tid < SP) af[tid] = v0p * psinv;
        __syncthreads();
        if (tid < 160) {
            float2 rsv = *(const float2*)&g_rs[(z0 * 4 + d0) * SP + 2 * tid];
            float a0 = af[2 * tid] * rsv.x, a1 = af[2 * tid + 1] * rsv.y;
            ah2[0][2 * tid]     = __floats2half2_rn(a0, a0);
            ah2[0][2 * tid + 1] = __floats2half2_rn(a1, a1);
        }
        __syncthreads();
    }

    int cb = (int)rank * 20 + w;
    int gcol = (int)rank * 160 + 8 * w + 2 * (lane & 3);
    int slot = (int)rank * 20 + w;
    int bit0 = lane & 1, bit1 = (lane >> 1) & 1;

    uint2 mr[10];
    {
        const uint2* base = (const uint2*)(g_S + (size_t)z0 * SPSP);
        #pragma unroll
        for (int k = 0; k < 10; k++) mr[k] = __ldcg(base + (k * 40 + cb) * 32 + lane);
    }

    for (int step = 0; step < NSTEP; ++step) {
        int pb = step & 1, nb = 1 - pb;
        int d = sg[step] & 3;
        int zn = sg[step + 1] >> 2;
        int dn = sg[step + 1] & 3;

        float tot = 0.f;
        #pragma unroll
        for (int q = 0; q < 10; q++) {
            float4 t = *(const float4*)&redp[nb][4 * q];
            tot += (t.x + t.y) + (t.z + t.w);
        }
        float si = __frcp_rn(tot);
        if (rank == 0 && tid == 0) {
            float y = logf(tot) - lcomp;
            float t2 = llf + y;
            lcomp = (t2 - llf) - y;
            llf = t2;
        }
        float2 fo  = *(const float2*)&g_BmT[d][gcol];
        float2 rsv = *(const float2*)&g_rs[(size_t)(zn * 4 + dn) * SP + gcol];

        __half2 a0 = __floats2half2_rn(0.f, 0.f);
        __half2 a1 = a0, a2 = a0, a3 = a0;
        #pragma unroll
        for (int k = 0; k < 10; k++) {
            __half2 av = ah2[pb][lane + 32 * k];
            a0 = __hfma2(av, u2h(__byte_perm(mr[k].x, 0, 0x1404)), a0);
            a1 = __hfma2(av, u2h(__byte_perm(mr[k].x, 0, 0x3424)), a1);
            a2 = __hfma2(av, u2h(__byte_perm(mr[k].y, 0, 0x1404)), a2);
            a3 = __hfma2(av, u2h(__byte_perm(mr[k].y, 0, 0x3424)), a3);
        }

        uint32_t h0 = h2u(a0), h1 = h2u(a1), h2v = h2u(a2), h3 = h2u(a3);
        {
            uint32_t g0 = bit0 ? h0 : h1, g1 = bit0 ? h2v : h3;
            uint32_t r0 = __shfl_xor_sync(0xffffffffu, g0, 1);
            uint32_t r1 = __shfl_xor_sync(0xffffffffu, g1, 1);
            h0 = hadd2u(bit0 ? h1 : h0, r0);
            h1 = hadd2u(bit0 ? h3 : h2v, r1);
        }
        {
            uint32_t g0 = bit1 ? h0 : h1;
            uint32_t r0 = __shfl_xor_sync(0xffffffffu, g0, 2);
            h0 = hadd2u(bit1 ? h1 : h0, r0);
        }
        h0 = hadd2u(h0, __shfl_xor_sync(0xffffffffu, h0, 4));
        h0 = hadd2u(h0, __shfl_xor_sync(0xffffffffu, h0, 8));
        h0 = hadd2u(h0, __shfl_xor_sync(0xffffffffu, h0, 16));

        float p = 0.f;
        if (lane < 4) {
            float2 f2 = __half22float2(u2h(h0));
            float v0 = f2.x * fo.x * si, v1 = f2.y * fo.y * si;
            float b0 = v0 * rsv.x, b1 = v1 * rsv.y;
            uint32_t pkx = h2u(__floats2half2_rn(b0, b0));
            uint32_t pky = h2u(__floats2half2_rn(b1, b1));
            *(uint2*)&ah2[nb][gcol] = make_uint2(pkx, pky);
            uint64_t vv = ((uint64_t)pky << 32) | pkx;
            uint32_t la = s2u(&ah2[nb][gcol]);
            asm volatile(
                "{ .reg .b32 ra; mapa.shared::cluster.u32 ra, %0, %1;"
                "  st.shared::cluster.b64 [ra], %2; }"
                :: "r"(la), "r"(peer), "l"(vv) : "memory");
            p = v0 + v1;
        }
        p += __shfl_xor_sync(0xffffffffu, p, 1);
        p += __shfl_xor_sync(0xffffffffu, p, 2);
        if (lane == 0) {
            redp[pb][slot] = p;
            uint32_t la = s2u(&redp[pb][slot]);
            asm volatile(
                "{ .reg .b32 ra; mapa.shared::cluster.u32 ra, %0, %1;"
                "  st.shared::cluster.b32 [ra], %2; }"
                :: "r"(la), "r"(peer), "f"(p) : "memory");
        }
        if (lane < 4) {
            asm volatile(
                "{ .reg .b32 ra; mapa.shared::cluster.u32 ra, %0, %1;"
                "  mbarrier.arrive.shared::cluster.b64 _, [ra]; }"
                :: "r"(mbarA), "r"(peer) : "memory");
        }
        asm volatile("mbarrier.arrive.shared.b64 _, [%0];" :: "r"(mbarA) : "memory");

        {
            const uint2* base = (const uint2*)(g_S + (size_t)zn * SPSP);
            #pragma unroll
            for (int k = 0; k < 10; k++) mr[k] = __ldcg(base + (k * 40 + cb) * 32 + lane);
        }

        {
            uint32_t parity = (uint32_t)(step & 1);
            uint32_t done;
            asm volatile(
                "{ .reg .pred P;"
                "  mbarrier.try_wait.parity.acquire.cluster.shared::cta.b64 P, [%1], %2;"
                "  selp.b32 %0, 1, 0, P; }"
                : "=r"(done) : "r"(mbarA), "r"(parity) : "memory");
            if (!done) {
                asm volatile(
                    "{ .reg .pred P;"
                    "WL_%=:"
                    "  mbarrier.try_wait.parity.acquire.cluster.shared::cta.b64 P, [%0], %1, 0x989680;"
                    "  @P bra WD_%=;"
                    "  bra WL_%=;"
                    "WD_%=: }"
                    :: "r"(mbarA), "r"(parity) : "memory");
            }
        }
    }

    if (rank == 0 && tid == 0) {
        int fb = (NSTEP - 1) & 1;
        float tot = 0.f;
        #pragma unroll
        for (int q = 0; q < 40; q++) tot += redp[fb][q];
        llf += logf(tot);
        out[b] = (float)((double)llf - (double)NSTEP * LOG_SCALE_D);
    }
}

// ---------------- launch ----------------
extern "C" void kernel_launch(void* const* d_in, const int* in_sizes, int n_in,
                              void* d_out, int out_size) {
    const float* inputs = (const float*)d_in[0];
    const float* initk  = (const float*)d_in[1];
    const float* transk = (const float*)d_in[2];
    const float* emisk  = (const float*)d_in[3];
    float* out = (float*)d_out;

    k_setup<<<1, 512>>>(initk, emisk);
    k_softA<<<NS, 320>>>(transk);
    k_gram<<<NB, 256>>>(inputs);
    k_gemm_h<<<dim3(5, 5, 4), 256>>>(0);     // Q_a
    k_gemm_h<<<dim3(5, 5, 16), 256>>>(1);    // U_cd
    k_gemm_h<<<dim3(5, 5, 256), 256>>>(2);   // M_abcd
    k_quant<<<dim3(40, 256), 256>>>();
    k_chain<<<NB * 2, 640>>>(out);
}

// round 17
// speedup vs baseline: 1.4054x; 1.0915x over previous
#include <cuda_runtime.h>
#include <cuda_fp16.h>
#include <cuda_fp8.h>
#include <mma.h>
#include <math.h>
#include <stdint.h>

using namespace nvcuda;

#define NS 305
#define SP 320
#define SPSP (SP * SP)
#define NB 64
#define NT 4096
#define NSTEP 819            // 5-gram supersteps: 1 + 5*819 = 4096 exactly
#define NMAT 256             // 4^4 composite matrices
#define LOG_SCALE_D 8.317766166719343   // log(4096)

// ---------------- device globals (zero-initialized) ----------------
__device__ float g_I[SP];
__device__ __align__(16) float g_BmT[4][SP];              // BmT[a][s] = Bm[s][a]
__device__ __align__(16) __half g_A16[SPSP];              // softmax(A), fp16
__device__ __align__(16) __half g_Q16[4][SPSP];           // Q_a = (A Da) A
__device__ __align__(16) __half g_U16[16][SPSP];          // U_cd = (Q_c Dd) A
__device__ __align__(16) __half g_M16[(size_t)NMAT * SPSP];  // M_abcd = (Q_a Db) U_cd
// e5m2 SINGLE copy (26 MB), 8-col BLOCKED layout:
// byte (r,c) at ((r>>5)*40 + (c>>3))*256 + (r&31)*8 + (c&7)
__device__ __align__(16) unsigned char g_S[(size_t)NMAT * SPSP];
// rs[(z*4+d)*SP + r] = 4096 * (sum_j BmT[d][j]*M[z][r][j]) / (sum_j BmT[d][j]*dec(S[z][r][j]))
__device__ __align__(16) float g_rs[NMAT * 4 * SP];
__device__ unsigned short g_gram[NB * NSTEP];             // (z<<2)|fold
__device__ unsigned char g_o0[NB];

__device__ __forceinline__ float warpSum(float x) {
    #pragma unroll
    for (int o = 16; o; o >>= 1) x += __shfl_down_sync(0xffffffffu, x, o);
    return x;
}
__device__ __forceinline__ float warpSumAll(float x) {
    #pragma unroll
    for (int o = 16; o; o >>= 1) x += __shfl_xor_sync(0xffffffffu, x, o);
    return x;
}
__device__ __forceinline__ float warpMax(float x) {
    #pragma unroll
    for (int o = 16; o; o >>= 1) x = fmaxf(x, __shfl_down_sync(0xffffffffu, x, o));
    return x;
}
__device__ __forceinline__ float warpMaxAll(float x) {
    #pragma unroll
    for (int o = 16; o; o >>= 1) x = fmaxf(x, __shfl_xor_sync(0xffffffffu, x, o));
    return x;
}
__device__ __forceinline__ __half2 u2h(uint32_t u) { return *reinterpret_cast<__half2*>(&u); }
__device__ __forceinline__ uint32_t h2u(__half2 h) { return *reinterpret_cast<uint32_t*>(&h); }
__device__ __forceinline__ uint32_t hadd2u(uint32_t a, uint32_t b) {
    return h2u(__hadd2(u2h(a), u2h(b)));
}
__device__ __forceinline__ uint32_t s2u(const void* p) {
    uint32_t a;
    asm("{ .reg .u64 t; cvta.to.shared.u64 t, %1; cvt.u32.u64 %0, t; }" : "=r"(a) : "l"(p));
    return a;
}

#define BAR_SYNC(id, n)   asm volatile("bar.sync %0, %1;"   :: "n"(id), "n"(n) : "memory")

#define MBAR_WAIT(MBARADDR, PAR)                                                 \
    {                                                                            \
        uint32_t done;                                                           \
        asm volatile(                                                            \
            "{ .reg .pred P;"                                                    \
            "  mbarrier.try_wait.parity.acquire.cluster.shared::cta.b64 P, [%1], %2;" \
            "  selp.b32 %0, 1, 0, P; }"                                          \
            : "=r"(done) : "r"(MBARADDR), "r"(PAR) : "memory");                  \
        if (!done) {                                                             \
            asm volatile(                                                        \
                "{ .reg .pred P;"                                                \
                "WL_%=:"                                                         \
                "  mbarrier.try_wait.parity.acquire.cluster.shared::cta.b64 P, [%0], %1, 0x989680;" \
                "  @P bra WD_%=;"                                                \
                "  bra WL_%=;"                                                   \
                "WD_%=: }"                                                       \
                :: "r"(MBARADDR), "r"(PAR) : "memory");                          \
        }                                                                        \
    }

// ---------------- setup: I softmax + emission softmax ----------------
__global__ void k_setup(const float* __restrict__ initk, const float* __restrict__ emisk) {
    __shared__ float red[16];
    __shared__ float bval;
    int tid = threadIdx.x, wid = tid >> 5, lane = tid & 31;
    const int nw = 16;
    float v = (tid < NS) ? initk[tid] : -1e30f;
    float m = warpMax(v);
    if (lane == 0) red[wid] = m;
    __syncthreads();
    if (tid == 0) { float mm = -1e30f; for (int w = 0; w < nw; w++) mm = fmaxf(mm, red[w]); bval = mm; }
    __syncthreads();
    m = bval;
    float e = (tid < NS) ? expf(v - m) : 0.f;
    float s = warpSum(e);
    __syncthreads();
    if (lane == 0) red[wid] = s;
    __syncthreads();
    if (tid == 0) { float ss = 0.f; for (int w = 0; w < nw; w++) ss += red[w]; bval = ss; }
    __syncthreads();
    if (tid < NS) g_I[tid] = e / bval;

    if (tid < NS) {
        float x0 = emisk[tid * 4 + 0], x1 = emisk[tid * 4 + 1];
        float x2 = emisk[tid * 4 + 2], x3 = emisk[tid * 4 + 3];
        float mm = fmaxf(fmaxf(x0, x1), fmaxf(x2, x3));
        float e0 = expf(x0 - mm), e1 = expf(x1 - mm), e2 = expf(x2 - mm), e3 = expf(x3 - mm);
        float inv = 1.f / (e0 + e1 + e2 + e3);
        g_BmT[0][tid] = e0 * inv; g_BmT[1][tid] = e1 * inv;
        g_BmT[2][tid] = e2 * inv; g_BmT[3][tid] = e3 * inv;
    }
}

// ---------------- softmax rows of transition -> A16 ----------------
__global__ void k_softA(const float* __restrict__ trans) {
    __shared__ float red[10];
    __shared__ float bval;
    int r = blockIdx.x, tid = threadIdx.x;
    int wid = tid >> 5, lane = tid & 31;
    float v = (tid < NS) ? trans[r * NS + tid] : -1e30f;
    float m = warpMax(v);
    if (lane == 0) red[wid] = m;
    __syncthreads();
    if (tid == 0) { float mm = -1e30f; for (int w = 0; w < 10; w++) mm = fmaxf(mm, red[w]); bval = mm; }
    __syncthreads();
    m = bval;
    float e = (tid < NS) ? expf(v - m) : 0.f;
    float s = warpSum(e);
    __syncthreads();
    if (lane == 0) red[wid] = s;
    __syncthreads();
    if (tid == 0) { float ss = 0.f; for (int w = 0; w < 10; w++) ss += red[w]; bval = ss; }
    __syncthreads();
    if (tid < NS) g_A16[r * SP + tid] = __float2half_rn(e / bval);
}

// ---------------- observation -> 5-gram indices ----------------
__global__ void k_gram(const float* __restrict__ inputs) {
    int b = blockIdx.x;
    const float* inb = inputs + (size_t)b * NT * 4;
    for (int tau = threadIdx.x; tau < NSTEP; tau += blockDim.x) {
        int t0 = 1 + 5 * tau;
        unsigned g = 0;
        #pragma unroll
        for (int k = 0; k < 5; k++) {
            const float* p = inb + (size_t)(t0 + k) * 4;
            float fi = p[1] + 2.f * p[2] + 3.f * p[3];   // exact argmax of one-hot
            g = (g << 2) | (unsigned)(fi + 0.5f);
        }
        g_gram[b * NSTEP + tau] = (unsigned short)g;
    }
    if (threadIdx.x == 0) {
        const float* p = inb;
        g_o0[b] = (unsigned char)(p[1] + 2.f * p[2] + 3.f * p[3] + 0.5f);
    }
}

// ---------------- wmma fp16 GEMM, vectorized + smem-unioned (R16) ----------------
__global__ void __launch_bounds__(256) k_gemm_h(int mode) {
    int z = blockIdx.z;
    const __half *Lp, *Rp;
    const float* sc;
    __half* outp;
    if (mode == 0)      { Lp = g_A16;        sc = g_BmT[z];           Rp = g_A16;        outp = g_Q16[z]; }
    else if (mode == 1) { Lp = g_Q16[z >> 2]; sc = g_BmT[z & 3];      Rp = g_A16;        outp = g_U16[z]; }
    else                { Lp = g_Q16[z >> 6]; sc = g_BmT[(z >> 4) & 3]; Rp = g_U16[z & 15]; outp = g_M16 + (size_t)z * SPSP; }
    int m0 = blockIdx.y * 64, n0 = blockIdx.x * 64;

    __shared__ __align__(16) char smem_buf[2 * 64 * 72 * 2];
    __half (*As)[72] = (__half(*)[72])smem_buf;
    __half (*Bs)[72] = (__half(*)[72])(smem_buf + 64 * 72 * 2);
    float (*Cs)[68] = (float(*)[68])smem_buf;                  // UNION

    int tid = threadIdx.x;
    int w = tid >> 5;
    int wm = w & 3, wn = w >> 2;
    int lr = tid >> 2, lc = (tid & 3) * 16;

    wmma::fragment<wmma::accumulator, 16, 16, 16, float> cf[2];
    wmma::fill_fragment(cf[0], 0.f);
    wmma::fill_fragment(cf[1], 0.f);

    for (int k0 = 0; k0 < SP; k0 += 64) {
        #pragma unroll
        for (int h = 0; h < 2; h++) {
            int c8 = lc + 8 * h;
            uint4 lv = *(const uint4*)&Lp[(size_t)(m0 + lr) * SP + k0 + c8];
            float4 s0 = *(const float4*)&sc[k0 + c8];
            float4 s1 = *(const float4*)&sc[k0 + c8 + 4];
            float2 f0 = __half22float2(u2h(lv.x));
            float2 f1 = __half22float2(u2h(lv.y));
            float2 f2 = __half22float2(u2h(lv.z));
            float2 f3 = __half22float2(u2h(lv.w));
            uint4 ov;
            ov.x = h2u(__floats2half2_rn(f0.x * s0.x, f0.y * s0.y));
            ov.y = h2u(__floats2half2_rn(f1.x * s0.z, f1.y * s0.w));
            ov.z = h2u(__floats2half2_rn(f2.x * s1.x, f2.y * s1.y));
            ov.w = h2u(__floats2half2_rn(f3.x * s1.z, f3.y * s1.w));
            *(uint4*)&As[lr][c8] = ov;
            *(uint4*)&Bs[lr][c8] = *(const uint4*)&Rp[(size_t)(k0 + lr) * SP + n0 + c8];
        }
        __syncthreads();
        #pragma unroll
        for (int kk = 0; kk < 4; kk++) {
            wmma::fragment<wmma::matrix_a, 16, 16, 16, __half, wmma::row_major> af;
            wmma::load_matrix_sync(af, &As[wm * 16][kk * 16], 72);
            #pragma unroll
            for (int nn = 0; nn < 2; nn++) {
                wmma::fragment<wmma::matrix_b, 16, 16, 16, __half, wmma::row_major> bf;
                wmma::load_matrix_sync(bf, &Bs[kk * 16][wn * 32 + nn * 16], 72);
                wmma::mma_sync(cf[nn], af, bf, cf[nn]);
            }
        }
        __syncthreads();
    }
    wmma::store_matrix_sync(&Cs[wm * 16][wn * 32 + 0], cf[0], 68, wmma::mem_row_major);
    wmma::store_matrix_sync(&Cs[wm * 16][wn * 32 + 16], cf[1], 68, wmma::mem_row_major);
    __syncthreads();
    {
        float4 c0 = *(const float4*)&Cs[lr][lc + 0];
        float4 c1 = *(const float4*)&Cs[lr][lc + 4];
        float4 c2 = *(const float4*)&Cs[lr][lc + 8];
        float4 c3 = *(const float4*)&Cs[lr][lc + 12];
        uint4 o0, o1;
        o0.x = h2u(__floats2half2_rn(c0.x, c0.y));
        o0.y = h2u(__floats2half2_rn(c0.z, c0.w));
        o0.z = h2u(__floats2half2_rn(c1.x, c1.y));
        o0.w = h2u(__floats2half2_rn(c1.z, c1.w));
        o1.x = h2u(__floats2half2_rn(c2.x, c2.y));
        o1.y = h2u(__floats2half2_rn(c2.z, c2.w));
        o1.z = h2u(__floats2half2_rn(c3.x, c3.y));
        o1.w = h2u(__floats2half2_rn(c3.z, c3.w));
        __half* op = outp + (size_t)(m0 + lr) * SP + n0 + lc;
        *(uint4*)op = o0;
        *(uint4*)(op + 8) = o1;
    }
}

// ---------------- quantize M to e5m2 + exact corrections (R16) ----------------
__global__ void k_quant() {
    int z = blockIdx.y;
    int warp = threadIdx.x >> 5, lane = threadIdx.x & 31;
    int r = blockIdx.x * 8 + warp;
    const __half* row = g_M16 + (size_t)z * SPSP + (size_t)r * SP;
    bool two = (lane < 8);
    int j0 = lane, j1 = 32 + lane;

    float f0[8], f1[8];
    {
        uint4 v = *(const uint4*)&row[8 * j0];
        float2 a = __half22float2(u2h(v.x)), b2 = __half22float2(u2h(v.y));
        float2 c = __half22float2(u2h(v.z)), e = __half22float2(u2h(v.w));
        f0[0] = a.x; f0[1] = a.y; f0[2] = b2.x; f0[3] = b2.y;
        f0[4] = c.x; f0[5] = c.y; f0[6] = e.x; f0[7] = e.y;
    }
    if (two) {
        uint4 v = *(const uint4*)&row[8 * j1];
        float2 a = __half22float2(u2h(v.x)), b2 = __half22float2(u2h(v.y));
        float2 c = __half22float2(u2h(v.z)), e = __half22float2(u2h(v.w));
        f1[0] = a.x; f1[1] = a.y; f1[2] = b2.x; f1[3] = b2.y;
        f1[4] = c.x; f1[5] = c.y; f1[6] = e.x; f1[7] = e.y;
    } else {
        #pragma unroll
        for (int i = 0; i < 8; i++) f1[i] = 0.f;
    }

    float mx = 0.f;
    #pragma unroll
    for (int i = 0; i < 8; i++) mx = fmaxf(mx, fmaxf(f0[i], f1[i]));
    mx = warpMaxAll(mx);
    float q = (mx > 0.f) ? 384.f / mx : 1.f;

    unsigned char* dst = g_S + (size_t)z * SPSP;
    int rk = r >> 5, rL = r & 31;

    float d0[8], d1[8];
    {
        uint2 pk;
        uint32_t b_ = 0;
        #pragma unroll
        for (int i = 0; i < 4; i++) {
            unsigned char byte = (unsigned char)__nv_cvt_float_to_fp8(f0[i] * q, __NV_SATFINITE, __NV_E5M2);
            d0[i] = __half2float(__ushort_as_half((unsigned short)(byte << 8)));
            b_ |= (uint32_t)byte << (8 * i);
        }
        pk.x = b_; b_ = 0;
        #pragma unroll
        for (int i = 0; i < 4; i++) {
            unsigned char byte = (unsigned char)__nv_cvt_float_to_fp8(f0[i + 4] * q, __NV_SATFINITE, __NV_E5M2);
            d0[i + 4] = __half2float(__ushort_as_half((unsigned short)(byte << 8)));
            b_ |= (uint32_t)byte << (8 * i);
        }
        pk.y = b_;
        *(uint2*)&dst[(((rk * 40 + j0) * 32 + rL) << 3)] = pk;
    }
    if (two) {
        uint2 pk;
        uint32_t b_ = 0;
        #pragma unroll
        for (int i = 0; i < 4; i++) {
            unsigned char byte = (unsigned char)__nv_cvt_float_to_fp8(f1[i] * q, __NV_SATFINITE, __NV_E5M2);
            d1[i] = __half2float(__ushort_as_half((unsigned short)(byte << 8)));
            b_ |= (uint32_t)byte << (8 * i);
        }
        pk.x = b_; b_ = 0;
        #pragma unroll
        for (int i = 0; i < 4; i++) {
            unsigned char byte = (unsigned char)__nv_cvt_float_to_fp8(f1[i + 4] * q, __NV_SATFINITE, __NV_E5M2);
            d1[i + 4] = __half2float(__ushort_as_half((unsigned short)(byte << 8)));
            b_ |= (uint32_t)byte << (8 * i);
        }
        pk.y = b_;
        *(uint2*)&dst[(((rk * 40 + j1) * 32 + rL) << 3)] = pk;
    } else {
        #pragma unroll
        for (int i = 0; i < 8; i++) d1[i] = 0.f;
    }

    #pragma unroll
    for (int d = 0; d < 4; d++) {
        float st = 0.f, sq = 0.f;
        float4 bm0a = *(const float4*)&g_BmT[d][8 * j0];
        float4 bm0b = *(const float4*)&g_BmT[d][8 * j0 + 4];
        st = fmaf(bm0a.x, f0[0], st); sq = fmaf(bm0a.x, d0[0], sq);
        st = fmaf(bm0a.y, f0[1], st); sq = fmaf(bm0a.y, d0[1], sq);
        st = fmaf(bm0a.z, f0[2], st); sq = fmaf(bm0a.z, d0[2], sq);
        st = fmaf(bm0a.w, f0[3], st); sq = fmaf(bm0a.w, d0[3], sq);
        st = fmaf(bm0b.x, f0[4], st); sq = fmaf(bm0b.x, d0[4], sq);
        st = fmaf(bm0b.y, f0[5], st); sq = fmaf(bm0b.y, d0[5], sq);
        st = fmaf(bm0b.z, f0[6], st); sq = fmaf(bm0b.z, d0[6], sq);
        st = fmaf(bm0b.w, f0[7], st); sq = fmaf(bm0b.w, d0[7], sq);
        if (two) {
            float4 bm1a = *(const float4*)&g_BmT[d][8 * j1];
            float4 bm1b = *(const float4*)&g_BmT[d][8 * j1 + 4];
            st = fmaf(bm1a.x, f1[0], st); sq = fmaf(bm1a.x, d1[0], sq);
            st = fmaf(bm1a.y, f1[1], st); sq = fmaf(bm1a.y, d1[1], sq);
            st = fmaf(bm1a.z, f1[2], st); sq = fmaf(bm1a.z, d1[2], sq);
            st = fmaf(bm1a.w, f1[3], st); sq = fmaf(bm1a.w, d1[3], sq);
            st = fmaf(bm1b.x, f1[4], st); sq = fmaf(bm1b.x, d1[4], sq);
            st = fmaf(bm1b.y, f1[5], st); sq = fmaf(bm1b.y, d1[5], sq);
            st = fmaf(bm1b.z, f1[6], st); sq = fmaf(bm1b.z, d1[6], sq);
            st = fmaf(bm1b.w, f1[7], st); sq = fmaf(bm1b.w, d1[7], sq);
        }
        st = warpSumAll(st);
        sq = warpSumAll(sq);
        if (lane == 0)
            g_rs[(z * 4 + d) * SP + r] = (sq > 0.f) ? 4096.f * st / sq : 0.f;
    }
}

// ---------------- chain: 2-CTA cluster, SPLIT-FMA sync overlap ----------------
// Step: [own-half FMA (rows from own rank's alpha, local-bar-visible)] -> mbar wait
// (previous phase; peer DSMEM flight hidden under own-half FMA) -> [remote-half FMA]
// -> si/log -> reduce -> alpha+redp publish (local + peer) + arrives -> next mr loads
// -> bar.sync (local visibility). Skew <= 1 step: phase s completes only after peer
// passed its phase s-1 wait => same-parity mbarrier reuse safe. Epilogue waits final phase.
#define FMA_HALF(K0)                                                             \
    {                                                                            \
        _Pragma("unroll")                                                        \
        for (int kk = 0; kk < 5; kk++) {                                         \
            const int k = (K0) + kk;                                             \
            __half2 av = ah2[pb][lane + 32 * k];                                 \
            a0 = __hfma2(av, u2h(__byte_perm(mr[k].x, 0, 0x1404)), a0);          \
            a1 = __hfma2(av, u2h(__byte_perm(mr[k].x, 0, 0x3424)), a1);          \
            a2 = __hfma2(av, u2h(__byte_perm(mr[k].y, 0, 0x1404)), a2);          \
            a3 = __hfma2(av, u2h(__byte_perm(mr[k].y, 0, 0x3424)), a3);          \
        }                                                                        \
    }

__global__ void __launch_bounds__(640, 1) __cluster_dims__(2, 1, 1)
k_chain(float* __restrict__ out) {
    int tid = threadIdx.x;
    int b = blockIdx.x >> 1;
    uint32_t rank;
    asm("mov.u32 %0, %%cluster_ctarank;" : "=r"(rank));
    int peer = 1 - (int)rank;

    __shared__ __half2 ah2[2][SP];
    __shared__ __align__(16) float redp[2][48];
    __shared__ unsigned short sg[NSTEP + 1];
    __shared__ __align__(8) uint64_t mbar;
    __shared__ float pr[20];
    __shared__ float psinv;
    __shared__ float af[SP];

    int lane = tid & 31, w = tid >> 5;
    uint32_t mbarA = s2u(&mbar);

    for (int i = tid; i < NSTEP; i += 640) sg[i] = g_gram[b * NSTEP + i];
    int o0 = g_o0[b];
    if (tid == 0) sg[NSTEP] = 0;
    if (tid < 48) { redp[0][tid] = 0.f; redp[1][tid] = (tid == 0) ? 1.f : 0.f; }
    if (tid == 0)
        asm volatile("mbarrier.init.shared.b64 [%0], %1;" :: "r"(mbarA), "r"(720) : "memory");
    __syncthreads();
    asm volatile("barrier.cluster.arrive.aligned;" ::: "memory");
    asm volatile("barrier.cluster.wait.aligned;" ::: "memory");

    int z0 = sg[0] >> 2, d0 = sg[0] & 3;

    // ---- prologue: both CTAs build the FULL normalized alpha0 (both halves local) ----
    float llf = 0.f, lcomp = 0.f;
    {
        float v0p = (tid < SP) ? g_I[tid] * g_BmT[o0][tid] : 0.f;
        float wsum = warpSum(v0p);
        if (lane == 0) pr[w] = wsum;
        __syncthreads();
        if (tid == 0) {
            float x = 0.f;
            #pragma unroll
            for (int q = 0; q < 20; q++) x += pr[q];
            psinv = 1.f / x;
            pr[0] = x;
        }
        __syncthreads();
        llf = logf(pr[0]);
        if (tid < SP) af[tid] = v0p * psinv;
        __syncthreads();
        if (tid < 160) {
            float2 rsv = *(const float2*)&g_rs[(z0 * 4 + d0) * SP + 2 * tid];
            float a0 = af[2 * tid] * rsv.x, a1 = af[2 * tid + 1] * rsv.y;
            ah2[0][2 * tid]     = __floats2half2_rn(a0, a0);
            ah2[0][2 * tid + 1] = __floats2half2_rn(a1, a1);
        }
        __syncthreads();
    }

    int cb = (int)rank * 20 + w;
    int gcol = (int)rank * 160 + 8 * w + 2 * (lane & 3);
    int slot = (int)rank * 20 + w;
    int bit0 = lane & 1, bit1 = (lane >> 1) & 1;
    int kOwn = (int)rank * 5;      // own-half k-iters (rows 160*rank..+160)
    int kOth = 5 - kOwn;           // the other half (peer-produced rows)

    uint2 mr[10];
    {
        const uint2* base = (const uint2*)(g_S + (size_t)z0 * SPSP);
        #pragma unroll
        for (int k = 0; k < 10; k++) mr[k] = __ldcg(base + (k * 40 + cb) * 32 + lane);
    }

    for (int step = 0; step < NSTEP; ++step) {
        int pb = step & 1, nb = 1 - pb;
        int d = sg[step] & 3;
        int zn = sg[step + 1] >> 2;
        int dn = sg[step + 1] & 3;

        float2 fo  = *(const float2*)&g_BmT[d][gcol];
        float2 rsv = *(const float2*)&g_rs[(size_t)(zn * 4 + dn) * SP + gcol];

        __half2 a0 = __floats2half2_rn(0.f, 0.f);
        __half2 a1 = a0, a2 = a0, a3 = a0;

        // ---- own-half FMA (rows produced by this CTA, visible via step-end bar.sync) ----
        if (rank == 0) FMA_HALF(0) else FMA_HALF(5)

        // ---- wait previous phase: peer's alpha-half + redp (hidden under FMA above) ----
        if (step > 0) {
            uint32_t parw = (uint32_t)((step + 1) & 1);   // = (step-1)&1
            MBAR_WAIT(mbarA, parw)
        }

        // ---- remote-half FMA ----
        if (rank == 0) FMA_HALF(5) else FMA_HALF(0)

        // ---- si from last step's 40 global partials (safe after wait) ----
        float tot = 0.f;
        #pragma unroll
        for (int q = 0; q < 10; q++) {
            float4 t = *(const float4*)&redp[nb][4 * q];
            tot += (t.x + t.y) + (t.z + t.w);
        }
        float si = __frcp_rn(tot);
        if (rank == 0 && tid == 0) {               // Kahan log of s_{step-1}
            float y = logf(tot) - lcomp;
            float t2 = llf + y;
            lcomp = (t2 - llf) - y;
            llf = t2;
        }

        // ---- in-warp reduce: lane ends holding col-pair (lane&3) total ----
        uint32_t h0 = h2u(a0), h1 = h2u(a1), h2v = h2u(a2), h3 = h2u(a3);
        {
            uint32_t g0 = bit0 ? h0 : h1, g1 = bit0 ? h2v : h3;
            uint32_t r0 = __shfl_xor_sync(0xffffffffu, g0, 1);
            uint32_t r1 = __shfl_xor_sync(0xffffffffu, g1, 1);
            h0 = hadd2u(bit0 ? h1 : h0, r0);
            h1 = hadd2u(bit0 ? h3 : h2v, r1);
        }
        {
            uint32_t g0 = bit1 ? h0 : h1;
            uint32_t r0 = __shfl_xor_sync(0xffffffffu, g0, 2);
            h0 = hadd2u(bit1 ? h1 : h0, r0);
        }
        h0 = hadd2u(h0, __shfl_xor_sync(0xffffffffu, h0, 4));
        h0 = hadd2u(h0, __shfl_xor_sync(0xffffffffu, h0, 8));
        h0 = hadd2u(h0, __shfl_xor_sync(0xffffffffu, h0, 16));

        // ---- lanes 0-3: finish own 2 cols, write local + remote alpha ----
        float p = 0.f;
        if (lane < 4) {
            float2 f2 = __half22float2(u2h(h0));
            float v0 = f2.x * fo.x * si, v1 = f2.y * fo.y * si;
            float b0 = v0 * rsv.x, b1 = v1 * rsv.y;
            uint32_t pkx = h2u(__floats2half2_rn(b0, b0));
            uint32_t pky = h2u(__floats2half2_rn(b1, b1));
            *(uint2*)&ah2[nb][gcol] = make_uint2(pkx, pky);
            uint64_t vv = ((uint64_t)pky << 32) | pkx;
            uint32_t la = s2u(&ah2[nb][gcol]);
            asm volatile(
                "{ .reg .b32 ra; mapa.shared::cluster.u32 ra, %0, %1;"
                "  st.shared::cluster.b64 [ra], %2; }"
                :: "r"(la), "r"(peer), "l"(vv) : "memory");
            p = v0 + v1;
        }
        p += __shfl_xor_sync(0xffffffffu, p, 1);
        p += __shfl_xor_sync(0xffffffffu, p, 2);
        if (lane == 0) {
            redp[pb][slot] = p;
            uint32_t la = s2u(&redp[pb][slot]);
            asm volatile(
                "{ .reg .b32 ra; mapa.shared::cluster.u32 ra, %0, %1;"
                "  st.shared::cluster.b32 [ra], %2; }"
                :: "r"(la), "r"(peer), "f"(p) : "memory");
        }
        if (lane < 4) {
            asm volatile(
                "{ .reg .b32 ra; mapa.shared::cluster.u32 ra, %0, %1;"
                "  mbarrier.arrive.shared::cluster.b64 _, [ra]; }"
                :: "r"(mbarA), "r"(peer) : "memory");
        }
        asm volatile("mbarrier.arrive.shared.b64 _, [%0];" :: "r"(mbarA) : "memory");

        // ---- issue next step's mr loads (latency covered by bar + next own-FMA) ----
        {
            const uint2* base = (const uint2*)(g_S + (size_t)zn * SPSP);
            #pragma unroll
            for (int k = 0; k < 10; k++) mr[k] = __ldcg(base + (k * 40 + cb) * 32 + lane);
        }

        BAR_SYNC(1, 640);        // local visibility: ah2[nb] own slices + redp[pb]
    }

    // final phase (NSTEP-1) must complete before reading its redp partials
    {
        uint32_t parw = (uint32_t)((NSTEP - 1) & 1);
        MBAR_WAIT(mbarA, parw)
    }
    if (rank == 0 && tid == 0) {
        int fb = (NSTEP - 1) & 1;
        float tot = 0.f;
        #pragma unroll
        for (int q = 0; q < 40; q++) tot += redp[fb][q];
        llf += logf(tot);
        out[b] = (float)((double)llf - (double)NSTEP * LOG_SCALE_D);
    }
}

// ---------------- launch ----------------
extern "C" void kernel_launch(void* const* d_in, const int* in_sizes, int n_in,
                              void* d_out, int out_size) {
    const float* inputs = (const float*)d_in[0];
    const float* initk  = (const float*)d_in[1];
    const float* transk = (const float*)d_in[2];
    const float* emisk  = (const float*)d_in[3];
    float* out = (float*)d_out;

    k_setup<<<1, 512>>>(initk, emisk);
    k_softA<<<NS, 320>>>(transk);
    k_gram<<<NB, 256>>>(inputs);
    k_gemm_h<<<dim3(5, 5, 4), 256>>>(0);     // Q_a
    k_gemm_h<<<dim3(5, 5, 16), 256>>>(1);    // U_cd
    k_gemm_h<<<dim3(5, 5, 256), 256>>>(2);   // M_abcd
    k_quant<<<dim3(40, 256), 256>>>();
    k_chain<<<NB * 2, 640>>>(out);
}